// round 8
// baseline (speedup 1.0000x reference)
#include <cuda_runtime.h>
#include <cuda_bf16.h>
#include <cstdint>

// Problem constants
#define BATCH 2
#define SEQ   2048
#define DMODEL 1024
#define NHEAD 16
#define HDIM  64
#define ROWS  (BATCH*SEQ)          // 4096
#define ELEMS (ROWS*DMODEL)        // 4,194,304
#define KEFF  3072                 // 3-term bf16 split K

// Scratch (static __device__ globals — allocation-free per harness rules)
__device__ float g_q[ELEMS];
__device__ float g_k[ELEMS];   // masked K (K')
__device__ float g_v[ELEMS];
__device__ float g_m[BATCH*NHEAD*HDIM*HDIM];   // 131072 floats
__device__ __nv_bfloat16 g_abar[(size_t)ROWS*KEFF];       // [4096,3072] 24MB
__device__ __nv_bfloat16 g_bbar[(size_t)3*DMODEL*KEFF];   // 3x[1024,3072] 18MB

// ---------------------------------------------------------------------------
// Base-target (sm_80+) PTX helpers: ldmatrix / mma.sync / cp.async
// ---------------------------------------------------------------------------
__device__ __forceinline__ uint32_t smem_to_u32(const void* p) {
    uint32_t a;
    asm("{ .reg .u64 t; cvta.to.shared.u64 t, %1; cvt.u32.u64 %0, t; }" : "=r"(a) : "l"(p));
    return a;
}
__device__ __forceinline__ void ldsm_x4(uint32_t& r0, uint32_t& r1, uint32_t& r2, uint32_t& r3,
                                        uint32_t addr) {
    asm volatile("ldmatrix.sync.aligned.m8n8.x4.shared.b16 {%0,%1,%2,%3}, [%4];"
                 : "=r"(r0), "=r"(r1), "=r"(r2), "=r"(r3) : "r"(addr));
}
__device__ __forceinline__ void mma_bf16(float* d, uint32_t a0, uint32_t a1, uint32_t a2,
                                         uint32_t a3, uint32_t b0, uint32_t b1) {
    asm volatile("mma.sync.aligned.m16n8k16.row.col.f32.bf16.bf16.f32 "
                 "{%0,%1,%2,%3}, {%4,%5,%6,%7}, {%8,%9}, {%0,%1,%2,%3};"
                 : "+f"(d[0]), "+f"(d[1]), "+f"(d[2]), "+f"(d[3])
                 : "r"(a0), "r"(a1), "r"(a2), "r"(a3), "r"(b0), "r"(b1));
}
#define CP_ASYNC16(saddr, gptr) \
    asm volatile("cp.async.cg.shared.global [%0], [%1], 16;" :: "r"(saddr), "l"(gptr))
#define CP_COMMIT() asm volatile("cp.async.commit_group;" ::: "memory")
#define CP_WAIT1()  asm volatile("cp.async.wait_group 1;" ::: "memory")
#define CP_WAIT0()  asm volatile("cp.async.wait_group 0;" ::: "memory")

// SW128 swizzle: rows of 128B, chunk16B index ^= (row & 7)
#define SWZ128(bo) ((bo) ^ (((bo) >> 3) & 0x70))

// ---------------------------------------------------------------------------
// node 0: X -> Abar = [hi | lo | hi] along K (bf16 split)
// ---------------------------------------------------------------------------
__global__ __launch_bounds__(256) void conv_x(const float* __restrict__ X)
{
    int t = blockIdx.x * 256 + threadIdx.x;
    int idx = t * 4;
    float4 v = *(const float4*)(X + idx);
    int r = idx >> 10, k = idx & 1023;
    float f[4] = {v.x, v.y, v.z, v.w};
    __nv_bfloat16 h[4], l[4];
#pragma unroll
    for (int i = 0; i < 4; i++) {
        h[i] = __float2bfloat16(f[i]);
        l[i] = __float2bfloat16(f[i] - __bfloat162float(h[i]));
    }
    __nv_bfloat16* base = g_abar + (size_t)r * KEFF;
    *(__nv_bfloat162*)(base + k)          = __nv_bfloat162(h[0], h[1]);
    *(__nv_bfloat162*)(base + k + 2)      = __nv_bfloat162(h[2], h[3]);
    *(__nv_bfloat162*)(base + 1024 + k)   = __nv_bfloat162(l[0], l[1]);
    *(__nv_bfloat162*)(base + 1024 + k+2) = __nv_bfloat162(l[2], l[3]);
    *(__nv_bfloat162*)(base + 2048 + k)   = __nv_bfloat162(h[0], h[1]);
    *(__nv_bfloat162*)(base + 2048 + k+2) = __nv_bfloat162(h[2], h[3]);
}

// node 1: W -> Bbar = [hi | hi | lo]
__global__ __launch_bounds__(256) void conv_w(const float* __restrict__ Wq,
                                              const float* __restrict__ Wk,
                                              const float* __restrict__ Wv)
{
    int which = blockIdx.y;
    const float* __restrict__ W = (which == 0) ? Wq : (which == 1) ? Wk : Wv;
    int t = blockIdx.x * 256 + threadIdx.x;
    int idx = t * 4;
    float4 v = *(const float4*)(W + idx);
    int r = idx >> 10, k = idx & 1023;
    float f[4] = {v.x, v.y, v.z, v.w};
    __nv_bfloat16 h[4], l[4];
#pragma unroll
    for (int i = 0; i < 4; i++) {
        h[i] = __float2bfloat16(f[i]);
        l[i] = __float2bfloat16(f[i] - __bfloat162float(h[i]));
    }
    __nv_bfloat16* base = g_bbar + (size_t)which * DMODEL * KEFF + (size_t)r * KEFF;
    *(__nv_bfloat162*)(base + k)          = __nv_bfloat162(h[0], h[1]);
    *(__nv_bfloat162*)(base + k + 2)      = __nv_bfloat162(h[2], h[3]);
    *(__nv_bfloat162*)(base + 1024 + k)   = __nv_bfloat162(h[0], h[1]);
    *(__nv_bfloat162*)(base + 1024 + k+2) = __nv_bfloat162(h[2], h[3]);
    *(__nv_bfloat162*)(base + 2048 + k)   = __nv_bfloat162(l[0], l[1]);
    *(__nv_bfloat162*)(base + 2048 + k+2) = __nv_bfloat162(l[2], l[3]);
}

// node 2: zero M accumulator
__global__ void zero_m()
{
    g_m[blockIdx.x * 256 + threadIdx.x] = 0.0f;
}

// ---------------------------------------------------------------------------
// node 3: mma.sync bf16 QKV projection. Y = Abar @ Bbar^T + bias (+ mask for K)
// CTA 128x128, BK=64, 8 warps (2x4), warp tile 64x32,
// 3-stage cp.async ring + register-fragment double buffering, 2 CTAs/SM.
// grid = (8, 32, 3), dynamic smem = 96KB
// ---------------------------------------------------------------------------
#define BKC 64
#define NITER (KEFF / BKC)   // 48
#define CHUNK_BYTES 16384    // 128 rows * 128B
#define BUF_BYTES   32768    // A chunk + B chunk
#define NSTAGE 3

__global__ __launch_bounds__(256, 2)
void qkv_mma(const float* __restrict__ amask,
             const float* __restrict__ bq,
             const float* __restrict__ bk,
             const float* __restrict__ bv)
{
    extern __shared__ __align__(1024) uint8_t smem[];
    __shared__ float sBias[128];

    const int tid  = threadIdx.x;
    const int wid  = tid >> 5;
    const int lane = tid & 31;
    const int which = blockIdx.z;
    const int m0 = blockIdx.y * 128;
    const int n0 = blockIdx.x * 128;

    const float* __restrict__ bias = (which == 0) ? bq : (which == 1) ? bk : bv;
    float* __restrict__ Y          = (which == 0) ? g_q : (which == 1) ? g_k : g_v;

    const __nv_bfloat16* __restrict__ Ag = g_abar;
    const __nv_bfloat16* __restrict__ Bg = g_bbar + (size_t)which * DMODEL * KEFF;

    const uint32_t sbase = smem_to_u32(smem);

    if (tid < 128) sBias[tid] = bias[n0 + tid];

    // staging: 256 threads x 4 passes cover 1024 16B-chunks per matrix
    const int srow = tid >> 3;        // 0..31
    const int sc   = tid & 7;         // 16B chunk within 128B row

    auto stage = [&](int it) {
        const int buf = it % NSTAGE;
        const int ke = it * BKC;
        const uint32_t abase = sbase + buf * BUF_BYTES;
        const uint32_t bbase = abase + CHUNK_BYTES;
#pragma unroll
        for (int p = 0; p < 4; p++) {
            const int row = srow + p * 32;
            const uint32_t so = SWZ128((uint32_t)(row * 128 + sc * 16));
            CP_ASYNC16(abase + so, Ag + (size_t)(m0 + row) * KEFF + ke + sc * 8);
            CP_ASYNC16(bbase + so, Bg + (size_t)(n0 + row) * KEFF + ke + sc * 8);
        }
    };

    // warp tiling: 2 warps along M, 4 along N
    const int wm0 = (wid & 1) * 64;
    const int wn0 = (wid >> 1) * 32;

    float acc[16][4];
#pragma unroll
    for (int i = 0; i < 16; i++)
#pragma unroll
        for (int j = 0; j < 4; j++) acc[i][j] = 0.0f;

    const int a_row = wm0 + (lane & 15);
    const int a_ch  = (lane >> 4);
    const int b_g   = lane >> 3;
    const int b_row = wn0 + ((b_g >> 1) << 3) + (lane & 7);
    const int b_ch  = (b_g & 1);

    // double-buffered register fragments
    uint32_t afr[2][4][4];
    uint32_t bfr[2][2][4];

    stage(0); CP_COMMIT();
    stage(1); CP_COMMIT();

    for (int it = 0; it < NITER; it++) {
        CP_WAIT1();
        __syncthreads();

        if (it + 2 < NITER) {
            stage(it + 2);
            CP_COMMIT();
        }

        const uint32_t abase = sbase + (it % NSTAGE) * BUF_BYTES;
        const uint32_t bbase = abase + CHUNK_BYTES;

        // prologue: load ks=0 fragments
#pragma unroll
        for (int mi = 0; mi < 4; mi++)
            ldsm_x4(afr[0][mi][0], afr[0][mi][1], afr[0][mi][2], afr[0][mi][3],
                    abase + SWZ128((uint32_t)((a_row + mi * 16) * 128 + a_ch * 16)));
#pragma unroll
        for (int np = 0; np < 2; np++)
            ldsm_x4(bfr[0][np][0], bfr[0][np][1], bfr[0][np][2], bfr[0][np][3],
                    bbase + SWZ128((uint32_t)((b_row + np * 16) * 128 + b_ch * 16)));

#pragma unroll
        for (int ks = 0; ks < 4; ks++) {
            const int cur = ks & 1, nxt = cur ^ 1;
            if (ks < 3) {
                const int ch_a = (ks + 1) * 2 + a_ch;
                const int ch_b = (ks + 1) * 2 + b_ch;
#pragma unroll
                for (int mi = 0; mi < 4; mi++)
                    ldsm_x4(afr[nxt][mi][0], afr[nxt][mi][1], afr[nxt][mi][2], afr[nxt][mi][3],
                            abase + SWZ128((uint32_t)((a_row + mi * 16) * 128 + ch_a * 16)));
#pragma unroll
                for (int np = 0; np < 2; np++)
                    ldsm_x4(bfr[nxt][np][0], bfr[nxt][np][1], bfr[nxt][np][2], bfr[nxt][np][3],
                            bbase + SWZ128((uint32_t)((b_row + np * 16) * 128 + ch_b * 16)));
            }
#pragma unroll
            for (int mi = 0; mi < 4; mi++)
#pragma unroll
                for (int ni = 0; ni < 4; ni++) {
                    const int np = ni >> 1, hf = (ni & 1) * 2;
                    mma_bf16(acc[mi * 4 + ni],
                             afr[cur][mi][0], afr[cur][mi][1], afr[cur][mi][2], afr[cur][mi][3],
                             bfr[cur][np][hf], bfr[cur][np][hf + 1]);
                }
        }
    }

    // Epilogue
    const int erow = wm0 + (lane >> 2);
    const int ecol = wn0 + (lane & 3) * 2;
#pragma unroll
    for (int mi = 0; mi < 4; mi++) {
        const int r0 = m0 + erow + mi * 16;
        const int r1 = r0 + 8;
        float mv0 = 1.0f, mv1 = 1.0f;
        if (which == 1) {
            mv0 = (amask[r0] >= 0.0f) ? 1.0f : 0.0f;
            mv1 = (amask[r1] >= 0.0f) ? 1.0f : 0.0f;
        }
#pragma unroll
        for (int ni = 0; ni < 4; ni++) {
            const int c = ecol + ni * 8;
            float* p0 = Y + (size_t)r0 * DMODEL + n0 + c;
            float* p1 = Y + (size_t)r1 * DMODEL + n0 + c;
            float2 o0, o1;
            o0.x = (acc[mi * 4 + ni][0] + sBias[c + 0]) * mv0;
            o0.y = (acc[mi * 4 + ni][1] + sBias[c + 1]) * mv0;
            o1.x = (acc[mi * 4 + ni][2] + sBias[c + 0]) * mv1;
            o1.y = (acc[mi * 4 + ni][3] + sBias[c + 1]) * mv1;
            *(float2*)p0 = o0;
            *(float2*)p1 = o1;
        }
    }
}

// ---------------------------------------------------------------------------
// node 4: M[b,h] += K'[b,h]^T @ V[b,h] over a 128-key slice (split-K + atomics)
// grid = (32, 16), 256 threads
// ---------------------------------------------------------------------------
__global__ __launch_bounds__(256)
void kv_outer()
{
    const int bh = blockIdx.x;
    const int b = bh >> 4, h = bh & 15;
    const int kstart = blockIdx.y * 128;

    __shared__ float Ks[32][64];
    __shared__ float Vs[32][64];

    const int tid = threadIdx.x;
    const int tx = tid & 15, ty = tid >> 4;

    float acc[4][4];
#pragma unroll
    for (int i = 0; i < 4; i++)
#pragma unroll
        for (int j = 0; j < 4; j++) acc[i][j] = 0.0f;

    const int lr = tid >> 3;
    const int lc = (tid & 7) * 8;

    for (int kc = 0; kc < 4; kc++) {
        const size_t base = (size_t)(b * SEQ + kstart + kc * 32 + lr) * DMODEL + h * HDIM + lc;
        float4 k0 = *(const float4*)(g_k + base);
        float4 k1 = *(const float4*)(g_k + base + 4);
        Ks[lr][lc + 0] = k0.x; Ks[lr][lc + 1] = k0.y; Ks[lr][lc + 2] = k0.z; Ks[lr][lc + 3] = k0.w;
        Ks[lr][lc + 4] = k1.x; Ks[lr][lc + 5] = k1.y; Ks[lr][lc + 6] = k1.z; Ks[lr][lc + 7] = k1.w;
        float4 v0 = *(const float4*)(g_v + base);
        float4 v1 = *(const float4*)(g_v + base + 4);
        Vs[lr][lc + 0] = v0.x; Vs[lr][lc + 1] = v0.y; Vs[lr][lc + 2] = v0.z; Vs[lr][lc + 3] = v0.w;
        Vs[lr][lc + 4] = v1.x; Vs[lr][lc + 5] = v1.y; Vs[lr][lc + 6] = v1.z; Vs[lr][lc + 7] = v1.w;
        __syncthreads();

#pragma unroll
        for (int kk = 0; kk < 32; kk++) {
            float a[4], bb[4];
#pragma unroll
            for (int i = 0; i < 4; i++) a[i]  = Ks[kk][ty * 4 + i];
#pragma unroll
            for (int j = 0; j < 4; j++) bb[j] = Vs[kk][tx * 4 + j];
#pragma unroll
            for (int i = 0; i < 4; i++)
#pragma unroll
                for (int j = 0; j < 4; j++)
                    acc[i][j] += a[i] * bb[j];
        }
        __syncthreads();
    }

    float* Mout = g_m + (size_t)bh * HDIM * HDIM;
#pragma unroll
    for (int i = 0; i < 4; i++)
#pragma unroll
        for (int j = 0; j < 4; j++)
            atomicAdd(&Mout[(ty * 4 + i) * HDIM + tx * 4 + j], acc[i][j]);
}

// ---------------------------------------------------------------------------
// node 5: ctx = Q @ M
// ---------------------------------------------------------------------------
__global__ __launch_bounds__(256)
void ctx_gemm(float* __restrict__ out)
{
    const int st = blockIdx.x, h = blockIdx.y, b = blockIdx.z;
    const int s0 = st * 64;

    __shared__ float Ms[64][64];
    __shared__ float Qt[64][72];

    const int tid = threadIdx.x;

    {
        const float* Msrc = g_m + (size_t)(b * NHEAD + h) * HDIM * HDIM;
        float* Md = &Ms[0][0];
#pragma unroll
        for (int i = 0; i < 4; i++) {
            int idx = tid * 16 + i * 4;
            *(float4*)(Md + idx) = *(const float4*)(Msrc + idx);
        }
    }
    {
        const int row = tid >> 2;
        const int cg  = (tid & 3) * 16;
        const size_t base = (size_t)(b * SEQ + s0 + row) * DMODEL + h * HDIM + cg;
#pragma unroll
        for (int i = 0; i < 4; i++) {
            float4 q = *(const float4*)(g_q + base + i * 4);
            Qt[cg + i * 4 + 0][row] = q.x;
            Qt[cg + i * 4 + 1][row] = q.y;
            Qt[cg + i * 4 + 2][row] = q.z;
            Qt[cg + i * 4 + 3][row] = q.w;
        }
    }
    __syncthreads();

    const int tx = tid & 15, ty = tid >> 4;
    float acc[4][4];
#pragma unroll
    for (int i = 0; i < 4; i++)
#pragma unroll
        for (int j = 0; j < 4; j++) acc[i][j] = 0.0f;

#pragma unroll
    for (int k = 0; k < 64; k++) {
        float a[4], bb[4];
#pragma unroll
        for (int i = 0; i < 4; i++) a[i]  = Qt[k][ty * 4 + i];
#pragma unroll
        for (int j = 0; j < 4; j++) bb[j] = Ms[k][tx * 4 + j];
#pragma unroll
        for (int i = 0; i < 4; i++)
#pragma unroll
            for (int j = 0; j < 4; j++)
                acc[i][j] += a[i] * bb[j];
    }

#pragma unroll
    for (int i = 0; i < 4; i++) {
        const int srow = s0 + ty * 4 + i;
#pragma unroll
        for (int j = 0; j < 4; j++) {
            const int col = h * HDIM + tx * 4 + j;
            out[(size_t)(b * SEQ + srow) * DMODEL + col] = acc[i][j];
        }
    }
}

// ---------------------------------------------------------------------------
extern "C" void kernel_launch(void* const* d_in, const int* in_sizes, int n_in,
                              void* d_out, int out_size)
{
    const float* X     = (const float*)d_in[0];
    const float* amask = (const float*)d_in[1];
    const float* Wq    = (const float*)d_in[2];
    const float* bq    = (const float*)d_in[3];
    const float* Wk    = (const float*)d_in[4];
    const float* bk    = (const float*)d_in[5];
    const float* Wv    = (const float*)d_in[6];
    const float* bv    = (const float*)d_in[7];
    float* out = (float*)d_out;

    cudaFuncSetAttribute(qkv_mma, cudaFuncAttributeMaxDynamicSharedMemorySize,
                         NSTAGE * BUF_BYTES);

    conv_x<<<ELEMS / 4 / 256, 256>>>(X);                                  // node 0
    conv_w<<<dim3(DMODEL * DMODEL / 4 / 256, 3), 256>>>(Wq, Wk, Wv);      // node 1
    zero_m<<<(BATCH * NHEAD * HDIM * HDIM) / 256, 256>>>();               // node 2
    qkv_mma<<<dim3(8, 32, 3), 256, NSTAGE * BUF_BYTES>>>(amask, bq, bk, bv); // node 3 (profiled)
    kv_outer<<<dim3(BATCH * NHEAD, 16), 256>>>();                         // node 4
    ctx_gemm<<<dim3(SEQ / 64, NHEAD, BATCH), 256>>>(out);                 // node 5
}

// round 9
// speedup vs baseline: 1.3519x; 1.3519x over previous
#include <cuda_runtime.h>
#include <cuda_fp16.h>
#include <cstdint>

// Problem constants
#define BATCH 2
#define SEQ   2048
#define DMODEL 1024
#define NHEAD 16
#define HDIM  64
#define ROWS  (BATCH*SEQ)          // 4096
#define ELEMS (ROWS*DMODEL)        // 4,194,304
#define KEFF  2048                 // 2-term fp16 split K

// Scratch (static __device__ globals — allocation-free per harness rules)
__device__ float g_q[ELEMS];
__device__ float g_k[ELEMS];   // masked K (K')
__device__ float g_v[ELEMS];
__device__ float g_m[BATCH*NHEAD*HDIM*HDIM];   // 131072 floats
__device__ __half g_abar[(size_t)ROWS*KEFF];       // [4096,2048] 16MB
__device__ __half g_bbar[(size_t)3*DMODEL*KEFF];   // 3x[1024,2048] 12MB

// ---------------------------------------------------------------------------
// Base-target (sm_80+) PTX helpers: ldmatrix / mma.sync / cp.async
// ---------------------------------------------------------------------------
__device__ __forceinline__ uint32_t smem_to_u32(const void* p) {
    uint32_t a;
    asm("{ .reg .u64 t; cvta.to.shared.u64 t, %1; cvt.u32.u64 %0, t; }" : "=r"(a) : "l"(p));
    return a;
}
__device__ __forceinline__ void ldsm_x4(uint32_t& r0, uint32_t& r1, uint32_t& r2, uint32_t& r3,
                                        uint32_t addr) {
    asm volatile("ldmatrix.sync.aligned.m8n8.x4.shared.b16 {%0,%1,%2,%3}, [%4];"
                 : "=r"(r0), "=r"(r1), "=r"(r2), "=r"(r3) : "r"(addr));
}
__device__ __forceinline__ void mma_f16(float* d, uint32_t a0, uint32_t a1, uint32_t a2,
                                        uint32_t a3, uint32_t b0, uint32_t b1) {
    asm volatile("mma.sync.aligned.m16n8k16.row.col.f32.f16.f16.f32 "
                 "{%0,%1,%2,%3}, {%4,%5,%6,%7}, {%8,%9}, {%0,%1,%2,%3};"
                 : "+f"(d[0]), "+f"(d[1]), "+f"(d[2]), "+f"(d[3])
                 : "r"(a0), "r"(a1), "r"(a2), "r"(a3), "r"(b0), "r"(b1));
}
#define CP_ASYNC16(saddr, gptr) \
    asm volatile("cp.async.cg.shared.global [%0], [%1], 16;" :: "r"(saddr), "l"(gptr))
#define CP_COMMIT() asm volatile("cp.async.commit_group;" ::: "memory")
#define CP_WAIT1()  asm volatile("cp.async.wait_group 1;" ::: "memory")
#define CP_WAIT0()  asm volatile("cp.async.wait_group 0;" ::: "memory")

// SW128 swizzle: rows of 128B, chunk16B index ^= (row & 7)
#define SWZ128(bo) ((bo) ^ (((bo) >> 3) & 0x70))

// ---------------------------------------------------------------------------
// node 0: X -> Abar = [hi | lo] along K (fp16 split)
// ---------------------------------------------------------------------------
__global__ __launch_bounds__(256) void conv_x(const float* __restrict__ X)
{
    int t = blockIdx.x * 256 + threadIdx.x;
    int idx = t * 4;
    float4 v = *(const float4*)(X + idx);
    int r = idx >> 10, k = idx & 1023;
    float f[4] = {v.x, v.y, v.z, v.w};
    __half h[4], l[4];
#pragma unroll
    for (int i = 0; i < 4; i++) {
        h[i] = __float2half(f[i]);
        l[i] = __float2half(f[i] - __half2float(h[i]));
    }
    __half* base = g_abar + (size_t)r * KEFF;
    *(__half2*)(base + k)          = __half2(h[0], h[1]);
    *(__half2*)(base + k + 2)      = __half2(h[2], h[3]);
    *(__half2*)(base + 1024 + k)   = __half2(l[0], l[1]);
    *(__half2*)(base + 1024 + k+2) = __half2(l[2], l[3]);
}

// node 1: W -> Bbar = [hi | hi]
__global__ __launch_bounds__(256) void conv_w(const float* __restrict__ Wq,
                                              const float* __restrict__ Wk,
                                              const float* __restrict__ Wv)
{
    int which = blockIdx.y;
    const float* __restrict__ W = (which == 0) ? Wq : (which == 1) ? Wk : Wv;
    int t = blockIdx.x * 256 + threadIdx.x;
    int idx = t * 4;
    float4 v = *(const float4*)(W + idx);
    int r = idx >> 10, k = idx & 1023;
    __half h[4] = {__float2half(v.x), __float2half(v.y),
                   __float2half(v.z), __float2half(v.w)};
    __half* base = g_bbar + (size_t)which * DMODEL * KEFF + (size_t)r * KEFF;
    *(__half2*)(base + k)          = __half2(h[0], h[1]);
    *(__half2*)(base + k + 2)      = __half2(h[2], h[3]);
    *(__half2*)(base + 1024 + k)   = __half2(h[0], h[1]);
    *(__half2*)(base + 1024 + k+2) = __half2(h[2], h[3]);
}

// node 2: zero M accumulator
__global__ void zero_m()
{
    g_m[blockIdx.x * 256 + threadIdx.x] = 0.0f;
}

// ---------------------------------------------------------------------------
// node 3: mma.sync fp16 QKV projection. Y = Abar @ Bbar^T + bias (+ mask for K)
// CTA 128x128, BK=64, 8 warps (2x4), warp tile 64x32, 2-stage cp.async,
// 2 CTAs/SM. grid = (8, 32, 3), dynamic smem = 64KB
// ---------------------------------------------------------------------------
#define BKC 64
#define NITER (KEFF / BKC)   // 32
#define CHUNK_BYTES 16384    // 128 rows * 128B
#define BUF_BYTES   32768    // A chunk + B chunk

__global__ __launch_bounds__(256, 2)
void qkv_mma(const float* __restrict__ amask,
             const float* __restrict__ bq,
             const float* __restrict__ bk,
             const float* __restrict__ bv)
{
    extern __shared__ __align__(1024) uint8_t smem[];
    __shared__ float sBias[128];

    const int tid  = threadIdx.x;
    const int wid  = tid >> 5;
    const int lane = tid & 31;
    const int which = blockIdx.z;
    const int m0 = blockIdx.y * 128;
    const int n0 = blockIdx.x * 128;

    const float* __restrict__ bias = (which == 0) ? bq : (which == 1) ? bk : bv;
    float* __restrict__ Y          = (which == 0) ? g_q : (which == 1) ? g_k : g_v;

    const __half* __restrict__ Ag = g_abar;
    const __half* __restrict__ Bg = g_bbar + (size_t)which * DMODEL * KEFF;

    const uint32_t sbase = smem_to_u32(smem);

    if (tid < 128) sBias[tid] = bias[n0 + tid];

    // staging: 256 threads x 4 passes cover 1024 16B-chunks per matrix
    const int srow = tid >> 3;        // 0..31
    const int sc   = tid & 7;         // 16B chunk within 128B row

    auto stage = [&](int buf, int it) {
        const int ke = it * BKC;
        const uint32_t abase = sbase + buf * BUF_BYTES;
        const uint32_t bbase = abase + CHUNK_BYTES;
#pragma unroll
        for (int p = 0; p < 4; p++) {
            const int row = srow + p * 32;
            const uint32_t so = SWZ128((uint32_t)(row * 128 + sc * 16));
            CP_ASYNC16(abase + so, Ag + (size_t)(m0 + row) * KEFF + ke + sc * 8);
            CP_ASYNC16(bbase + so, Bg + (size_t)(n0 + row) * KEFF + ke + sc * 8);
        }
    };

    // warp tiling: 2 warps along M, 4 along N
    const int wm0 = (wid & 1) * 64;
    const int wn0 = (wid >> 1) * 32;

    float acc[16][4];
#pragma unroll
    for (int i = 0; i < 16; i++)
#pragma unroll
        for (int j = 0; j < 4; j++) acc[i][j] = 0.0f;

    const int a_row = wm0 + (lane & 15);
    const int a_ch  = (lane >> 4);
    const int b_g   = lane >> 3;
    const int b_row = wn0 + ((b_g >> 1) << 3) + (lane & 7);
    const int b_ch  = (b_g & 1);

    stage(0, 0);
    CP_COMMIT();

    for (int it = 0; it < NITER; it++) {
        if (it + 1 < NITER) {
            stage((it + 1) & 1, it + 1);
            CP_COMMIT();
            CP_WAIT1();
        } else {
            CP_WAIT0();
        }
        __syncthreads();

        const uint32_t abase = sbase + (it & 1) * BUF_BYTES;
        const uint32_t bbase = abase + CHUNK_BYTES;

#pragma unroll
        for (int ks = 0; ks < 4; ks++) {
            uint32_t a[4][4];
#pragma unroll
            for (int mi = 0; mi < 4; mi++) {
                const int row = a_row + mi * 16;
                const int ch  = ks * 2 + a_ch;
                ldsm_x4(a[mi][0], a[mi][1], a[mi][2], a[mi][3],
                        abase + SWZ128((uint32_t)(row * 128 + ch * 16)));
            }
            uint32_t b[2][4];
#pragma unroll
            for (int np = 0; np < 2; np++) {
                const int row = b_row + np * 16;
                const int ch  = ks * 2 + b_ch;
                ldsm_x4(b[np][0], b[np][1], b[np][2], b[np][3],
                        bbase + SWZ128((uint32_t)(row * 128 + ch * 16)));
            }
#pragma unroll
            for (int mi = 0; mi < 4; mi++)
#pragma unroll
                for (int ni = 0; ni < 4; ni++) {
                    const int np = ni >> 1, hf = (ni & 1) * 2;
                    mma_f16(acc[mi * 4 + ni], a[mi][0], a[mi][1], a[mi][2], a[mi][3],
                            b[np][hf], b[np][hf + 1]);
                }
        }
        __syncthreads();
    }

    // Epilogue
    const int erow = wm0 + (lane >> 2);
    const int ecol = wn0 + (lane & 3) * 2;
#pragma unroll
    for (int mi = 0; mi < 4; mi++) {
        const int r0 = m0 + erow + mi * 16;
        const int r1 = r0 + 8;
        float mv0 = 1.0f, mv1 = 1.0f;
        if (which == 1) {
            mv0 = (amask[r0] >= 0.0f) ? 1.0f : 0.0f;
            mv1 = (amask[r1] >= 0.0f) ? 1.0f : 0.0f;
        }
#pragma unroll
        for (int ni = 0; ni < 4; ni++) {
            const int c = ecol + ni * 8;
            float* p0 = Y + (size_t)r0 * DMODEL + n0 + c;
            float* p1 = Y + (size_t)r1 * DMODEL + n0 + c;
            float2 o0, o1;
            o0.x = (acc[mi * 4 + ni][0] + sBias[c + 0]) * mv0;
            o0.y = (acc[mi * 4 + ni][1] + sBias[c + 1]) * mv0;
            o1.x = (acc[mi * 4 + ni][2] + sBias[c + 0]) * mv1;
            o1.y = (acc[mi * 4 + ni][3] + sBias[c + 1]) * mv1;
            *(float2*)p0 = o0;
            *(float2*)p1 = o1;
        }
    }
}

// ---------------------------------------------------------------------------
// node 4: M[b,h] += K'[b,h]^T @ V[b,h] over a 128-key slice (split-K + atomics)
// grid = (32, 16), 256 threads
// ---------------------------------------------------------------------------
__global__ __launch_bounds__(256)
void kv_outer()
{
    const int bh = blockIdx.x;
    const int b = bh >> 4, h = bh & 15;
    const int kstart = blockIdx.y * 128;

    __shared__ float Ks[32][64];
    __shared__ float Vs[32][64];

    const int tid = threadIdx.x;
    const int tx = tid & 15, ty = tid >> 4;

    float acc[4][4];
#pragma unroll
    for (int i = 0; i < 4; i++)
#pragma unroll
        for (int j = 0; j < 4; j++) acc[i][j] = 0.0f;

    const int lr = tid >> 3;
    const int lc = (tid & 7) * 8;

    for (int kc = 0; kc < 4; kc++) {
        const size_t base = (size_t)(b * SEQ + kstart + kc * 32 + lr) * DMODEL + h * HDIM + lc;
        float4 k0 = *(const float4*)(g_k + base);
        float4 k1 = *(const float4*)(g_k + base + 4);
        Ks[lr][lc + 0] = k0.x; Ks[lr][lc + 1] = k0.y; Ks[lr][lc + 2] = k0.z; Ks[lr][lc + 3] = k0.w;
        Ks[lr][lc + 4] = k1.x; Ks[lr][lc + 5] = k1.y; Ks[lr][lc + 6] = k1.z; Ks[lr][lc + 7] = k1.w;
        float4 v0 = *(const float4*)(g_v + base);
        float4 v1 = *(const float4*)(g_v + base + 4);
        Vs[lr][lc + 0] = v0.x; Vs[lr][lc + 1] = v0.y; Vs[lr][lc + 2] = v0.z; Vs[lr][lc + 3] = v0.w;
        Vs[lr][lc + 4] = v1.x; Vs[lr][lc + 5] = v1.y; Vs[lr][lc + 6] = v1.z; Vs[lr][lc + 7] = v1.w;
        __syncthreads();

#pragma unroll
        for (int kk = 0; kk < 32; kk++) {
            float a[4], bb[4];
#pragma unroll
            for (int i = 0; i < 4; i++) a[i]  = Ks[kk][ty * 4 + i];
#pragma unroll
            for (int j = 0; j < 4; j++) bb[j] = Vs[kk][tx * 4 + j];
#pragma unroll
            for (int i = 0; i < 4; i++)
#pragma unroll
                for (int j = 0; j < 4; j++)
                    acc[i][j] += a[i] * bb[j];
        }
        __syncthreads();
    }

    float* Mout = g_m + (size_t)bh * HDIM * HDIM;
#pragma unroll
    for (int i = 0; i < 4; i++)
#pragma unroll
        for (int j = 0; j < 4; j++)
            atomicAdd(&Mout[(ty * 4 + i) * HDIM + tx * 4 + j], acc[i][j]);
}

// ---------------------------------------------------------------------------
// node 5: ctx = Q @ M
// ---------------------------------------------------------------------------
__global__ __launch_bounds__(256)
void ctx_gemm(float* __restrict__ out)
{
    const int st = blockIdx.x, h = blockIdx.y, b = blockIdx.z;
    const int s0 = st * 64;

    __shared__ float Ms[64][64];
    __shared__ float Qt[64][72];

    const int tid = threadIdx.x;

    {
        const float* Msrc = g_m + (size_t)(b * NHEAD + h) * HDIM * HDIM;
        float* Md = &Ms[0][0];
#pragma unroll
        for (int i = 0; i < 4; i++) {
            int idx = tid * 16 + i * 4;
            *(float4*)(Md + idx) = *(const float4*)(Msrc + idx);
        }
    }
    {
        const int row = tid >> 2;
        const int cg  = (tid & 3) * 16;
        const size_t base = (size_t)(b * SEQ + s0 + row) * DMODEL + h * HDIM + cg;
#pragma unroll
        for (int i = 0; i < 4; i++) {
            float4 q = *(const float4*)(g_q + base + i * 4);
            Qt[cg + i * 4 + 0][row] = q.x;
            Qt[cg + i * 4 + 1][row] = q.y;
            Qt[cg + i * 4 + 2][row] = q.z;
            Qt[cg + i * 4 + 3][row] = q.w;
        }
    }
    __syncthreads();

    const int tx = tid & 15, ty = tid >> 4;
    float acc[4][4];
#pragma unroll
    for (int i = 0; i < 4; i++)
#pragma unroll
        for (int j = 0; j < 4; j++) acc[i][j] = 0.0f;

#pragma unroll
    for (int k = 0; k < 64; k++) {
        float a[4], bb[4];
#pragma unroll
        for (int i = 0; i < 4; i++) a[i]  = Qt[k][ty * 4 + i];
#pragma unroll
        for (int j = 0; j < 4; j++) bb[j] = Ms[k][tx * 4 + j];
#pragma unroll
        for (int i = 0; i < 4; i++)
#pragma unroll
            for (int j = 0; j < 4; j++)
                acc[i][j] += a[i] * bb[j];
    }

#pragma unroll
    for (int i = 0; i < 4; i++) {
        const int srow = s0 + ty * 4 + i;
#pragma unroll
        for (int j = 0; j < 4; j++) {
            const int col = h * HDIM + tx * 4 + j;
            out[(size_t)(b * SEQ + srow) * DMODEL + col] = acc[i][j];
        }
    }
}

// ---------------------------------------------------------------------------
extern "C" void kernel_launch(void* const* d_in, const int* in_sizes, int n_in,
                              void* d_out, int out_size)
{
    const float* X     = (const float*)d_in[0];
    const float* amask = (const float*)d_in[1];
    const float* Wq    = (const float*)d_in[2];
    const float* bq    = (const float*)d_in[3];
    const float* Wk    = (const float*)d_in[4];
    const float* bk    = (const float*)d_in[5];
    const float* Wv    = (const float*)d_in[6];
    const float* bv    = (const float*)d_in[7];
    float* out = (float*)d_out;

    cudaFuncSetAttribute(qkv_mma, cudaFuncAttributeMaxDynamicSharedMemorySize,
                         2 * BUF_BYTES);

    conv_x<<<ELEMS / 4 / 256, 256>>>(X);                                  // node 0
    conv_w<<<dim3(DMODEL * DMODEL / 4 / 256, 3), 256>>>(Wq, Wk, Wv);      // node 1
    zero_m<<<(BATCH * NHEAD * HDIM * HDIM) / 256, 256>>>();               // node 2
    qkv_mma<<<dim3(8, 32, 3), 256, 2 * BUF_BYTES>>>(amask, bq, bk, bv);   // node 3 (profiled)
    kv_outer<<<dim3(BATCH * NHEAD, 16), 256>>>();                         // node 4
    ctx_gemm<<<dim3(SEQ / 64, NHEAD, BATCH), 256>>>(out);                 // node 5
}

// round 10
// speedup vs baseline: 1.3605x; 1.0064x over previous
#include <cuda_runtime.h>
#include <cuda_fp16.h>
#include <cstdint>

// Problem constants
#define BATCH 2
#define SEQ   2048
#define DMODEL 1024
#define NHEAD 16
#define HDIM  64
#define ROWS  (BATCH*SEQ)          // 4096
#define ELEMS (ROWS*DMODEL)        // 4,194,304
#define KEFF  2048                 // 2-term fp16 split K

// Scratch (static __device__ globals — allocation-free per harness rules)
__device__ float g_q[ELEMS];
__device__ float g_k[ELEMS];   // masked K (K')
__device__ float g_v[ELEMS];
__device__ float g_m[BATCH*NHEAD*HDIM*HDIM];   // 131072 floats
__device__ __half g_abar[(size_t)ROWS*KEFF];       // [4096,2048] 16MB
__device__ __half g_bbar[(size_t)3*DMODEL*KEFF];   // 3x[1024,2048] 12MB

// ---------------------------------------------------------------------------
// Base-target (sm_80+) PTX helpers: ldmatrix / mma.sync / cp.async
// ---------------------------------------------------------------------------
__device__ __forceinline__ uint32_t smem_to_u32(const void* p) {
    uint32_t a;
    asm("{ .reg .u64 t; cvta.to.shared.u64 t, %1; cvt.u32.u64 %0, t; }" : "=r"(a) : "l"(p));
    return a;
}
__device__ __forceinline__ void ldsm_x4(uint32_t& r0, uint32_t& r1, uint32_t& r2, uint32_t& r3,
                                        uint32_t addr) {
    asm volatile("ldmatrix.sync.aligned.m8n8.x4.shared.b16 {%0,%1,%2,%3}, [%4];"
                 : "=r"(r0), "=r"(r1), "=r"(r2), "=r"(r3) : "r"(addr));
}
__device__ __forceinline__ void mma_f16(float* d, uint32_t a0, uint32_t a1, uint32_t a2,
                                        uint32_t a3, uint32_t b0, uint32_t b1) {
    asm volatile("mma.sync.aligned.m16n8k16.row.col.f32.f16.f16.f32 "
                 "{%0,%1,%2,%3}, {%4,%5,%6,%7}, {%8,%9}, {%0,%1,%2,%3};"
                 : "+f"(d[0]), "+f"(d[1]), "+f"(d[2]), "+f"(d[3])
                 : "r"(a0), "r"(a1), "r"(a2), "r"(a3), "r"(b0), "r"(b1));
}
#define CP_ASYNC16(saddr, gptr) \
    asm volatile("cp.async.cg.shared.global [%0], [%1], 16;" :: "r"(saddr), "l"(gptr))
#define CP_COMMIT() asm volatile("cp.async.commit_group;" ::: "memory")
#define CP_WAIT1()  asm volatile("cp.async.wait_group 1;" ::: "memory")
#define CP_WAIT0()  asm volatile("cp.async.wait_group 0;" ::: "memory")

// SW128 swizzle: rows of 128B, chunk16B index ^= (row & 7)
#define SWZ128(bo) ((bo) ^ (((bo) >> 3) & 0x70))

// ---------------------------------------------------------------------------
// node 0: X -> Abar = [hi | lo] along K (fp16 split). Also zeroes g_m.
// ---------------------------------------------------------------------------
__global__ __launch_bounds__(256) void conv_x(const float* __restrict__ X)
{
    if (blockIdx.x < 512) g_m[blockIdx.x * 256 + threadIdx.x] = 0.0f;

    int t = blockIdx.x * 256 + threadIdx.x;
    int idx = t * 4;
    float4 v = *(const float4*)(X + idx);
    int r = idx >> 10, k = idx & 1023;
    float f[4] = {v.x, v.y, v.z, v.w};
    __half h[4], l[4];
#pragma unroll
    for (int i = 0; i < 4; i++) {
        h[i] = __float2half(f[i]);
        l[i] = __float2half(f[i] - __half2float(h[i]));
    }
    __half* base = g_abar + (size_t)r * KEFF;
    *(__half2*)(base + k)          = __half2(h[0], h[1]);
    *(__half2*)(base + k + 2)      = __half2(h[2], h[3]);
    *(__half2*)(base + 1024 + k)   = __half2(l[0], l[1]);
    *(__half2*)(base + 1024 + k+2) = __half2(l[2], l[3]);
}

// node 1: W -> Bbar = [hi | hi]
__global__ __launch_bounds__(256) void conv_w(const float* __restrict__ Wq,
                                              const float* __restrict__ Wk,
                                              const float* __restrict__ Wv)
{
    int which = blockIdx.y;
    const float* __restrict__ W = (which == 0) ? Wq : (which == 1) ? Wk : Wv;
    int t = blockIdx.x * 256 + threadIdx.x;
    int idx = t * 4;
    float4 v = *(const float4*)(W + idx);
    int r = idx >> 10, k = idx & 1023;
    __half h[4] = {__float2half(v.x), __float2half(v.y),
                   __float2half(v.z), __float2half(v.w)};
    __half* base = g_bbar + (size_t)which * DMODEL * KEFF + (size_t)r * KEFF;
    *(__half2*)(base + k)          = __half2(h[0], h[1]);
    *(__half2*)(base + k + 2)      = __half2(h[2], h[3]);
    *(__half2*)(base + 1024 + k)   = __half2(h[0], h[1]);
    *(__half2*)(base + 1024 + k+2) = __half2(h[2], h[3]);
}

// ---------------------------------------------------------------------------
// node 2: mma.sync fp16 QKV projection. Y = Abar @ Bbar^T + bias (+ mask for K)
// CTA 128x128, BK=64, 8 warps (2x4), warp tile 64x32, 2-stage cp.async,
// 2 CTAs/SM. grid = (8, 32, 3), dynamic smem = 64KB
// ---------------------------------------------------------------------------
#define BKC 64
#define NITER (KEFF / BKC)   // 32
#define CHUNK_BYTES 16384    // 128 rows * 128B
#define BUF_BYTES   32768    // A chunk + B chunk

__global__ __launch_bounds__(256, 2)
void qkv_mma(const float* __restrict__ amask,
             const float* __restrict__ bq,
             const float* __restrict__ bk,
             const float* __restrict__ bv)
{
    extern __shared__ __align__(1024) uint8_t smem[];
    __shared__ float sBias[128];

    const int tid  = threadIdx.x;
    const int wid  = tid >> 5;
    const int lane = tid & 31;
    const int which = blockIdx.z;
    const int m0 = blockIdx.y * 128;
    const int n0 = blockIdx.x * 128;

    const float* __restrict__ bias = (which == 0) ? bq : (which == 1) ? bk : bv;
    float* __restrict__ Y          = (which == 0) ? g_q : (which == 1) ? g_k : g_v;

    const __half* __restrict__ Ag = g_abar;
    const __half* __restrict__ Bg = g_bbar + (size_t)which * DMODEL * KEFF;

    const uint32_t sbase = smem_to_u32(smem);

    if (tid < 128) sBias[tid] = bias[n0 + tid];

    // staging: 256 threads x 4 passes cover 1024 16B-chunks per matrix
    const int srow = tid >> 3;        // 0..31
    const int sc   = tid & 7;         // 16B chunk within 128B row

    auto stage = [&](int buf, int it) {
        const int ke = it * BKC;
        const uint32_t abase = sbase + buf * BUF_BYTES;
        const uint32_t bbase = abase + CHUNK_BYTES;
#pragma unroll
        for (int p = 0; p < 4; p++) {
            const int row = srow + p * 32;
            const uint32_t so = SWZ128((uint32_t)(row * 128 + sc * 16));
            CP_ASYNC16(abase + so, Ag + (size_t)(m0 + row) * KEFF + ke + sc * 8);
            CP_ASYNC16(bbase + so, Bg + (size_t)(n0 + row) * KEFF + ke + sc * 8);
        }
    };

    // warp tiling: 2 warps along M, 4 along N
    const int wm0 = (wid & 1) * 64;
    const int wn0 = (wid >> 1) * 32;

    float acc[16][4];
#pragma unroll
    for (int i = 0; i < 16; i++)
#pragma unroll
        for (int j = 0; j < 4; j++) acc[i][j] = 0.0f;

    const int a_row = wm0 + (lane & 15);
    const int a_ch  = (lane >> 4);
    const int b_g   = lane >> 3;
    const int b_row = wn0 + ((b_g >> 1) << 3) + (lane & 7);
    const int b_ch  = (b_g & 1);

    stage(0, 0);
    CP_COMMIT();

    for (int it = 0; it < NITER; it++) {
        if (it + 1 < NITER) {
            stage((it + 1) & 1, it + 1);
            CP_COMMIT();
            CP_WAIT1();
        } else {
            CP_WAIT0();
        }
        __syncthreads();

        const uint32_t abase = sbase + (it & 1) * BUF_BYTES;
        const uint32_t bbase = abase + CHUNK_BYTES;

#pragma unroll
        for (int ks = 0; ks < 4; ks++) {
            uint32_t a[4][4];
#pragma unroll
            for (int mi = 0; mi < 4; mi++) {
                const int row = a_row + mi * 16;
                const int ch  = ks * 2 + a_ch;
                ldsm_x4(a[mi][0], a[mi][1], a[mi][2], a[mi][3],
                        abase + SWZ128((uint32_t)(row * 128 + ch * 16)));
            }
            uint32_t b[2][4];
#pragma unroll
            for (int np = 0; np < 2; np++) {
                const int row = b_row + np * 16;
                const int ch  = ks * 2 + b_ch;
                ldsm_x4(b[np][0], b[np][1], b[np][2], b[np][3],
                        bbase + SWZ128((uint32_t)(row * 128 + ch * 16)));
            }
#pragma unroll
            for (int mi = 0; mi < 4; mi++)
#pragma unroll
                for (int ni = 0; ni < 4; ni++) {
                    const int np = ni >> 1, hf = (ni & 1) * 2;
                    mma_f16(acc[mi * 4 + ni], a[mi][0], a[mi][1], a[mi][2], a[mi][3],
                            b[np][hf], b[np][hf + 1]);
                }
        }
        __syncthreads();
    }

    // Epilogue
    const int erow = wm0 + (lane >> 2);
    const int ecol = wn0 + (lane & 3) * 2;
#pragma unroll
    for (int mi = 0; mi < 4; mi++) {
        const int r0 = m0 + erow + mi * 16;
        const int r1 = r0 + 8;
        float mv0 = 1.0f, mv1 = 1.0f;
        if (which == 1) {
            mv0 = (amask[r0] >= 0.0f) ? 1.0f : 0.0f;
            mv1 = (amask[r1] >= 0.0f) ? 1.0f : 0.0f;
        }
#pragma unroll
        for (int ni = 0; ni < 4; ni++) {
            const int c = ecol + ni * 8;
            float* p0 = Y + (size_t)r0 * DMODEL + n0 + c;
            float* p1 = Y + (size_t)r1 * DMODEL + n0 + c;
            float2 o0, o1;
            o0.x = (acc[mi * 4 + ni][0] + sBias[c + 0]) * mv0;
            o0.y = (acc[mi * 4 + ni][1] + sBias[c + 1]) * mv0;
            o1.x = (acc[mi * 4 + ni][2] + sBias[c + 0]) * mv1;
            o1.y = (acc[mi * 4 + ni][3] + sBias[c + 1]) * mv1;
            *(float2*)p0 = o0;
            *(float2*)p1 = o1;
        }
    }
}

// ---------------------------------------------------------------------------
// node 3: M[b,h] += K'[b,h]^T @ V[b,h] over a 128-key slice (split-K + atomics)
// grid = (32, 16), 256 threads, float4 shared loads in inner loop
// ---------------------------------------------------------------------------
__global__ __launch_bounds__(256)
void kv_outer()
{
    const int bh = blockIdx.x;
    const int b = bh >> 4, h = bh & 15;
    const int kstart = blockIdx.y * 128;

    __shared__ float Ks[32][64];
    __shared__ float Vs[32][64];

    const int tid = threadIdx.x;
    const int tx = tid & 15, ty = tid >> 4;

    float acc[4][4];
#pragma unroll
    for (int i = 0; i < 4; i++)
#pragma unroll
        for (int j = 0; j < 4; j++) acc[i][j] = 0.0f;

    const int lr = tid >> 3;
    const int lc = (tid & 7) * 8;

    for (int kc = 0; kc < 4; kc++) {
        const size_t base = (size_t)(b * SEQ + kstart + kc * 32 + lr) * DMODEL + h * HDIM + lc;
        *(float4*)(&Ks[lr][lc])     = *(const float4*)(g_k + base);
        *(float4*)(&Ks[lr][lc + 4]) = *(const float4*)(g_k + base + 4);
        *(float4*)(&Vs[lr][lc])     = *(const float4*)(g_v + base);
        *(float4*)(&Vs[lr][lc + 4]) = *(const float4*)(g_v + base + 4);
        __syncthreads();

#pragma unroll
        for (int kk = 0; kk < 32; kk++) {
            const float4 a4 = *(const float4*)(&Ks[kk][ty * 4]);
            const float4 b4 = *(const float4*)(&Vs[kk][tx * 4]);
            const float a[4] = {a4.x, a4.y, a4.z, a4.w};
            const float bb[4] = {b4.x, b4.y, b4.z, b4.w};
#pragma unroll
            for (int i = 0; i < 4; i++)
#pragma unroll
                for (int j = 0; j < 4; j++)
                    acc[i][j] += a[i] * bb[j];
        }
        __syncthreads();
    }

    float* Mout = g_m + (size_t)bh * HDIM * HDIM;
#pragma unroll
    for (int i = 0; i < 4; i++)
#pragma unroll
        for (int j = 0; j < 4; j++)
            atomicAdd(&Mout[(ty * 4 + i) * HDIM + tx * 4 + j], acc[i][j]);
}

// ---------------------------------------------------------------------------
// node 4: ctx = Q @ M  (float4 shared loads in inner loop)
// ---------------------------------------------------------------------------
__global__ __launch_bounds__(256)
void ctx_gemm(float* __restrict__ out)
{
    const int st = blockIdx.x, h = blockIdx.y, b = blockIdx.z;
    const int s0 = st * 64;

    __shared__ float Ms[64][64];
    __shared__ float Qt[64][72];

    const int tid = threadIdx.x;

    {
        const float* Msrc = g_m + (size_t)(b * NHEAD + h) * HDIM * HDIM;
        float* Md = &Ms[0][0];
#pragma unroll
        for (int i = 0; i < 4; i++) {
            int idx = tid * 16 + i * 4;
            *(float4*)(Md + idx) = *(const float4*)(Msrc + idx);
        }
    }
    {
        const int row = tid >> 2;
        const int cg  = (tid & 3) * 16;
        const size_t base = (size_t)(b * SEQ + s0 + row) * DMODEL + h * HDIM + cg;
#pragma unroll
        for (int i = 0; i < 4; i++) {
            float4 q = *(const float4*)(g_q + base + i * 4);
            Qt[cg + i * 4 + 0][row] = q.x;
            Qt[cg + i * 4 + 1][row] = q.y;
            Qt[cg + i * 4 + 2][row] = q.z;
            Qt[cg + i * 4 + 3][row] = q.w;
        }
    }
    __syncthreads();

    const int tx = tid & 15, ty = tid >> 4;
    float acc[4][4];
#pragma unroll
    for (int i = 0; i < 4; i++)
#pragma unroll
        for (int j = 0; j < 4; j++) acc[i][j] = 0.0f;

#pragma unroll
    for (int k = 0; k < 64; k++) {
        const float4 a4 = *(const float4*)(&Qt[k][ty * 4]);
        const float4 b4 = *(const float4*)(&Ms[k][tx * 4]);
        const float a[4] = {a4.x, a4.y, a4.z, a4.w};
        const float bb[4] = {b4.x, b4.y, b4.z, b4.w};
#pragma unroll
        for (int i = 0; i < 4; i++)
#pragma unroll
            for (int j = 0; j < 4; j++)
                acc[i][j] += a[i] * bb[j];
    }

#pragma unroll
    for (int i = 0; i < 4; i++) {
        const int srow = s0 + ty * 4 + i;
#pragma unroll
        for (int j = 0; j < 4; j++) {
            const int col = h * HDIM + tx * 4 + j;
            out[(size_t)(b * SEQ + srow) * DMODEL + col] = acc[i][j];
        }
    }
}

// ---------------------------------------------------------------------------
extern "C" void kernel_launch(void* const* d_in, const int* in_sizes, int n_in,
                              void* d_out, int out_size)
{
    const float* X     = (const float*)d_in[0];
    const float* amask = (const float*)d_in[1];
    const float* Wq    = (const float*)d_in[2];
    const float* bq    = (const float*)d_in[3];
    const float* Wk    = (const float*)d_in[4];
    const float* bk    = (const float*)d_in[5];
    const float* Wv    = (const float*)d_in[6];
    const float* bv    = (const float*)d_in[7];
    float* out = (float*)d_out;

    cudaFuncSetAttribute(qkv_mma, cudaFuncAttributeMaxDynamicSharedMemorySize,
                         2 * BUF_BYTES);

    conv_x<<<ELEMS / 4 / 256, 256>>>(X);                                  // node 0 (+zero_m)
    conv_w<<<dim3(DMODEL * DMODEL / 4 / 256, 3), 256>>>(Wq, Wk, Wv);      // node 1
    qkv_mma<<<dim3(8, 32, 3), 256, 2 * BUF_BYTES>>>(amask, bq, bk, bv);   // node 2
    kv_outer<<<dim3(BATCH * NHEAD, 16), 256>>>();                         // node 3
    ctx_gemm<<<dim3(SEQ / 64, NHEAD, BATCH), 256>>>(out);                 // node 4
}

// round 11
// speedup vs baseline: 1.3732x; 1.0094x over previous
#include <cuda_runtime.h>
#include <cuda_fp16.h>
#include <cstdint>

// Problem constants
#define BATCH 2
#define SEQ   2048
#define DMODEL 1024
#define NHEAD 16
#define HDIM  64
#define ROWS  (BATCH*SEQ)          // 4096
#define ELEMS (ROWS*DMODEL)        // 4,194,304
#define KEFF  2048                 // 2-term fp16 split K

// Scratch (static __device__ globals — allocation-free per harness rules)
__device__ float g_q[ELEMS];
__device__ float g_k[ELEMS];   // masked K (K')
__device__ float g_v[ELEMS];
__device__ float g_m[BATCH*NHEAD*HDIM*HDIM];   // 131072 floats
__device__ __half g_abar[(size_t)ROWS*KEFF];       // [4096,2048] 16MB
__device__ __half g_bbar[(size_t)3*DMODEL*KEFF];   // 3x[1024,2048] 12MB

// ---------------------------------------------------------------------------
// Base-target (sm_80+) PTX helpers: ldmatrix / mma.sync / cp.async
// ---------------------------------------------------------------------------
__device__ __forceinline__ uint32_t smem_to_u32(const void* p) {
    uint32_t a;
    asm("{ .reg .u64 t; cvta.to.shared.u64 t, %1; cvt.u32.u64 %0, t; }" : "=r"(a) : "l"(p));
    return a;
}
__device__ __forceinline__ void ldsm_x4(uint32_t& r0, uint32_t& r1, uint32_t& r2, uint32_t& r3,
                                        uint32_t addr) {
    asm volatile("ldmatrix.sync.aligned.m8n8.x4.shared.b16 {%0,%1,%2,%3}, [%4];"
                 : "=r"(r0), "=r"(r1), "=r"(r2), "=r"(r3) : "r"(addr));
}
__device__ __forceinline__ void mma_f16(float* d, uint32_t a0, uint32_t a1, uint32_t a2,
                                        uint32_t a3, uint32_t b0, uint32_t b1) {
    asm volatile("mma.sync.aligned.m16n8k16.row.col.f32.f16.f16.f32 "
                 "{%0,%1,%2,%3}, {%4,%5,%6,%7}, {%8,%9}, {%0,%1,%2,%3};"
                 : "+f"(d[0]), "+f"(d[1]), "+f"(d[2]), "+f"(d[3])
                 : "r"(a0), "r"(a1), "r"(a2), "r"(a3), "r"(b0), "r"(b1));
}
#define CP_ASYNC16(saddr, gptr) \
    asm volatile("cp.async.cg.shared.global [%0], [%1], 16;" :: "r"(saddr), "l"(gptr))
#define CP_COMMIT() asm volatile("cp.async.commit_group;" ::: "memory")
#define CP_WAIT1()  asm volatile("cp.async.wait_group 1;" ::: "memory")
#define CP_WAIT0()  asm volatile("cp.async.wait_group 0;" ::: "memory")

// SW128 swizzle: rows of 128B, chunk16B index ^= (row & 7)
#define SWZ128(bo) ((bo) ^ (((bo) >> 3) & 0x70))

// ---------------------------------------------------------------------------
// X -> Abar = [hi | lo] along K (fp16 split). Also zeroes g_m.
// ---------------------------------------------------------------------------
__global__ __launch_bounds__(256) void conv_x(const float* __restrict__ X)
{
    if (blockIdx.x < 512) g_m[blockIdx.x * 256 + threadIdx.x] = 0.0f;

    int t = blockIdx.x * 256 + threadIdx.x;
    int idx = t * 4;
    float4 v = *(const float4*)(X + idx);
    int r = idx >> 10, k = idx & 1023;
    float f[4] = {v.x, v.y, v.z, v.w};
    __half h[4], l[4];
#pragma unroll
    for (int i = 0; i < 4; i++) {
        h[i] = __float2half(f[i]);
        l[i] = __float2half(f[i] - __half2float(h[i]));
    }
    __half* base = g_abar + (size_t)r * KEFF;
    *(__half2*)(base + k)          = __half2(h[0], h[1]);
    *(__half2*)(base + k + 2)      = __half2(h[2], h[3]);
    *(__half2*)(base + 1024 + k)   = __half2(l[0], l[1]);
    *(__half2*)(base + 1024 + k+2) = __half2(l[2], l[3]);
}

// W -> Bbar = [hi | hi]
__global__ __launch_bounds__(256) void conv_w(const float* __restrict__ Wq,
                                              const float* __restrict__ Wk,
                                              const float* __restrict__ Wv)
{
    int which = blockIdx.y;
    const float* __restrict__ W = (which == 0) ? Wq : (which == 1) ? Wk : Wv;
    int t = blockIdx.x * 256 + threadIdx.x;
    int idx = t * 4;
    float4 v = *(const float4*)(W + idx);
    int r = idx >> 10, k = idx & 1023;
    __half h[4] = {__float2half(v.x), __float2half(v.y),
                   __float2half(v.z), __float2half(v.w)};
    __half* base = g_bbar + (size_t)which * DMODEL * KEFF + (size_t)r * KEFF;
    *(__half2*)(base + k)          = __half2(h[0], h[1]);
    *(__half2*)(base + k + 2)      = __half2(h[2], h[3]);
    *(__half2*)(base + 1024 + k)   = __half2(h[0], h[1]);
    *(__half2*)(base + 1024 + k+2) = __half2(h[2], h[3]);
}

// ---------------------------------------------------------------------------
// mma.sync fp16 projection. Y = Abar @ Bbar[slab]^T + bias (+ mask for K)
// slab = blockIdx.z + zbase: 0 -> g_q(+bq), 1 -> g_k(mask,+bk), 2 -> g_v(+bv)
// CTA 128x128, BK=64, 8 warps (2x4), warp tile 64x32, 2-stage cp.async,
// 2 CTAs/SM. dynamic smem = 64KB
// ---------------------------------------------------------------------------
#define BKC 64
#define NITER (KEFF / BKC)   // 32
#define CHUNK_BYTES 16384    // 128 rows * 128B
#define BUF_BYTES   32768    // A chunk + B chunk

__global__ __launch_bounds__(256, 2)
void qkv_mma(int zbase,
             const float* __restrict__ amask,
             const float* __restrict__ bq,
             const float* __restrict__ bk,
             const float* __restrict__ bv)
{
    extern __shared__ __align__(1024) uint8_t smem[];
    __shared__ float sBias[128];

    const int tid  = threadIdx.x;
    const int wid  = tid >> 5;
    const int lane = tid & 31;
    const int which = blockIdx.z + zbase;
    const int m0 = blockIdx.y * 128;
    const int n0 = blockIdx.x * 128;

    const float* __restrict__ bias = (which == 0) ? bq : (which == 1) ? bk : bv;
    float* __restrict__ Y          = (which == 0) ? g_q : (which == 1) ? g_k : g_v;

    const __half* __restrict__ Ag = g_abar;
    const __half* __restrict__ Bg = g_bbar + (size_t)which * DMODEL * KEFF;

    const uint32_t sbase = smem_to_u32(smem);

    if (tid < 128) sBias[tid] = bias[n0 + tid];

    // staging: 256 threads x 4 passes cover 1024 16B-chunks per matrix
    const int srow = tid >> 3;        // 0..31
    const int sc   = tid & 7;         // 16B chunk within 128B row

    auto stage = [&](int buf, int it) {
        const int ke = it * BKC;
        const uint32_t abase = sbase + buf * BUF_BYTES;
        const uint32_t bbase = abase + CHUNK_BYTES;
#pragma unroll
        for (int p = 0; p < 4; p++) {
            const int row = srow + p * 32;
            const uint32_t so = SWZ128((uint32_t)(row * 128 + sc * 16));
            CP_ASYNC16(abase + so, Ag + (size_t)(m0 + row) * KEFF + ke + sc * 8);
            CP_ASYNC16(bbase + so, Bg + (size_t)(n0 + row) * KEFF + ke + sc * 8);
        }
    };

    // warp tiling: 2 warps along M, 4 along N
    const int wm0 = (wid & 1) * 64;
    const int wn0 = (wid >> 1) * 32;

    float acc[16][4];
#pragma unroll
    for (int i = 0; i < 16; i++)
#pragma unroll
        for (int j = 0; j < 4; j++) acc[i][j] = 0.0f;

    const int a_row = wm0 + (lane & 15);
    const int a_ch  = (lane >> 4);
    const int b_g   = lane >> 3;
    const int b_row = wn0 + ((b_g >> 1) << 3) + (lane & 7);
    const int b_ch  = (b_g & 1);

    stage(0, 0);
    CP_COMMIT();

    for (int it = 0; it < NITER; it++) {
        if (it + 1 < NITER) {
            stage((it + 1) & 1, it + 1);
            CP_COMMIT();
            CP_WAIT1();
        } else {
            CP_WAIT0();
        }
        __syncthreads();

        const uint32_t abase = sbase + (it & 1) * BUF_BYTES;
        const uint32_t bbase = abase + CHUNK_BYTES;

#pragma unroll
        for (int ks = 0; ks < 4; ks++) {
            uint32_t a[4][4];
#pragma unroll
            for (int mi = 0; mi < 4; mi++) {
                const int row = a_row + mi * 16;
                const int ch  = ks * 2 + a_ch;
                ldsm_x4(a[mi][0], a[mi][1], a[mi][2], a[mi][3],
                        abase + SWZ128((uint32_t)(row * 128 + ch * 16)));
            }
            uint32_t b[2][4];
#pragma unroll
            for (int np = 0; np < 2; np++) {
                const int row = b_row + np * 16;
                const int ch  = ks * 2 + b_ch;
                ldsm_x4(b[np][0], b[np][1], b[np][2], b[np][3],
                        bbase + SWZ128((uint32_t)(row * 128 + ch * 16)));
            }
#pragma unroll
            for (int mi = 0; mi < 4; mi++)
#pragma unroll
                for (int ni = 0; ni < 4; ni++) {
                    const int np = ni >> 1, hf = (ni & 1) * 2;
                    mma_f16(acc[mi * 4 + ni], a[mi][0], a[mi][1], a[mi][2], a[mi][3],
                            b[np][hf], b[np][hf + 1]);
                }
        }
        __syncthreads();
    }

    // Epilogue
    const int erow = wm0 + (lane >> 2);
    const int ecol = wn0 + (lane & 3) * 2;
#pragma unroll
    for (int mi = 0; mi < 4; mi++) {
        const int r0 = m0 + erow + mi * 16;
        const int r1 = r0 + 8;
        float mv0 = 1.0f, mv1 = 1.0f;
        if (which == 1) {
            mv0 = (amask[r0] >= 0.0f) ? 1.0f : 0.0f;
            mv1 = (amask[r1] >= 0.0f) ? 1.0f : 0.0f;
        }
#pragma unroll
        for (int ni = 0; ni < 4; ni++) {
            const int c = ecol + ni * 8;
            float* p0 = Y + (size_t)r0 * DMODEL + n0 + c;
            float* p1 = Y + (size_t)r1 * DMODEL + n0 + c;
            float2 o0, o1;
            o0.x = (acc[mi * 4 + ni][0] + sBias[c + 0]) * mv0;
            o0.y = (acc[mi * 4 + ni][1] + sBias[c + 1]) * mv0;
            o1.x = (acc[mi * 4 + ni][2] + sBias[c + 0]) * mv1;
            o1.y = (acc[mi * 4 + ni][3] + sBias[c + 1]) * mv1;
            *(float2*)p0 = o0;
            *(float2*)p1 = o1;
        }
    }
}

// ---------------------------------------------------------------------------
// M[b,h] += K'[b,h]^T @ V[b,h] over a 128-key slice (split-K + atomics)
// grid = (32, 16), 256 threads
// ---------------------------------------------------------------------------
__global__ __launch_bounds__(256)
void kv_outer()
{
    const int bh = blockIdx.x;
    const int b = bh >> 4, h = bh & 15;
    const int kstart = blockIdx.y * 128;

    __shared__ float Ks[32][64];
    __shared__ float Vs[32][64];

    const int tid = threadIdx.x;
    const int tx = tid & 15, ty = tid >> 4;

    float acc[4][4];
#pragma unroll
    for (int i = 0; i < 4; i++)
#pragma unroll
        for (int j = 0; j < 4; j++) acc[i][j] = 0.0f;

    const int lr = tid >> 3;
    const int lc = (tid & 7) * 8;

    for (int kc = 0; kc < 4; kc++) {
        const size_t base = (size_t)(b * SEQ + kstart + kc * 32 + lr) * DMODEL + h * HDIM + lc;
        *(float4*)(&Ks[lr][lc])     = *(const float4*)(g_k + base);
        *(float4*)(&Ks[lr][lc + 4]) = *(const float4*)(g_k + base + 4);
        *(float4*)(&Vs[lr][lc])     = *(const float4*)(g_v + base);
        *(float4*)(&Vs[lr][lc + 4]) = *(const float4*)(g_v + base + 4);
        __syncthreads();

#pragma unroll
        for (int kk = 0; kk < 32; kk++) {
            const float4 a4 = *(const float4*)(&Ks[kk][ty * 4]);
            const float4 b4 = *(const float4*)(&Vs[kk][tx * 4]);
            const float a[4] = {a4.x, a4.y, a4.z, a4.w};
            const float bb[4] = {b4.x, b4.y, b4.z, b4.w};
#pragma unroll
            for (int i = 0; i < 4; i++)
#pragma unroll
                for (int j = 0; j < 4; j++)
                    acc[i][j] += a[i] * bb[j];
        }
        __syncthreads();
    }

    float* Mout = g_m + (size_t)bh * HDIM * HDIM;
#pragma unroll
    for (int i = 0; i < 4; i++)
#pragma unroll
        for (int j = 0; j < 4; j++)
            atomicAdd(&Mout[(ty * 4 + i) * HDIM + tx * 4 + j], acc[i][j]);
}

// ---------------------------------------------------------------------------
// ctx = Q @ M
// ---------------------------------------------------------------------------
__global__ __launch_bounds__(256)
void ctx_gemm(float* __restrict__ out)
{
    const int st = blockIdx.x, h = blockIdx.y, b = blockIdx.z;
    const int s0 = st * 64;

    __shared__ float Ms[64][64];
    __shared__ float Qt[64][72];

    const int tid = threadIdx.x;

    {
        const float* Msrc = g_m + (size_t)(b * NHEAD + h) * HDIM * HDIM;
        float* Md = &Ms[0][0];
#pragma unroll
        for (int i = 0; i < 4; i++) {
            int idx = tid * 16 + i * 4;
            *(float4*)(Md + idx) = *(const float4*)(Msrc + idx);
        }
    }
    {
        const int row = tid >> 2;
        const int cg  = (tid & 3) * 16;
        const size_t base = (size_t)(b * SEQ + s0 + row) * DMODEL + h * HDIM + cg;
#pragma unroll
        for (int i = 0; i < 4; i++) {
            float4 q = *(const float4*)(g_q + base + i * 4);
            Qt[cg + i * 4 + 0][row] = q.x;
            Qt[cg + i * 4 + 1][row] = q.y;
            Qt[cg + i * 4 + 2][row] = q.z;
            Qt[cg + i * 4 + 3][row] = q.w;
        }
    }
    __syncthreads();

    const int tx = tid & 15, ty = tid >> 4;
    float acc[4][4];
#pragma unroll
    for (int i = 0; i < 4; i++)
#pragma unroll
        for (int j = 0; j < 4; j++) acc[i][j] = 0.0f;

#pragma unroll
    for (int k = 0; k < 64; k++) {
        const float4 a4 = *(const float4*)(&Qt[k][ty * 4]);
        const float4 b4 = *(const float4*)(&Ms[k][tx * 4]);
        const float a[4] = {a4.x, a4.y, a4.z, a4.w};
        const float bb[4] = {b4.x, b4.y, b4.z, b4.w};
#pragma unroll
        for (int i = 0; i < 4; i++)
#pragma unroll
            for (int j = 0; j < 4; j++)
                acc[i][j] += a[i] * bb[j];
    }

#pragma unroll
    for (int i = 0; i < 4; i++) {
        const int srow = s0 + ty * 4 + i;
#pragma unroll
        for (int j = 0; j < 4; j++) {
            const int col = h * HDIM + tx * 4 + j;
            out[(size_t)(b * SEQ + srow) * DMODEL + col] = acc[i][j];
        }
    }
}

// ---------------------------------------------------------------------------
// Launch: two-branch graph.
//   branch KV (s_kv): conv_x -> qkv(K,V) -> kv_outer
//   branch Q  (s_q) : conv_w -> qkv(Q)
//   join: ctx_gemm on the capture (default) stream.
// Streams/events are host-side objects created once; no device allocations.
// ---------------------------------------------------------------------------
extern "C" void kernel_launch(void* const* d_in, const int* in_sizes, int n_in,
                              void* d_out, int out_size)
{
    const float* X     = (const float*)d_in[0];
    const float* amask = (const float*)d_in[1];
    const float* Wq    = (const float*)d_in[2];
    const float* bq    = (const float*)d_in[3];
    const float* Wk    = (const float*)d_in[4];
    const float* bk    = (const float*)d_in[5];
    const float* Wv    = (const float*)d_in[6];
    const float* bv    = (const float*)d_in[7];
    float* out = (float*)d_out;

    static cudaStream_t s_kv = nullptr, s_q = nullptr;
    static cudaEvent_t ev_fork = nullptr, ev_convx = nullptr, ev_convw = nullptr,
                       ev_kv = nullptr, ev_q = nullptr;
    if (s_kv == nullptr) {
        cudaStreamCreateWithFlags(&s_kv, cudaStreamNonBlocking);
        cudaStreamCreateWithFlags(&s_q,  cudaStreamNonBlocking);
        cudaEventCreateWithFlags(&ev_fork,  cudaEventDisableTiming);
        cudaEventCreateWithFlags(&ev_convx, cudaEventDisableTiming);
        cudaEventCreateWithFlags(&ev_convw, cudaEventDisableTiming);
        cudaEventCreateWithFlags(&ev_kv,    cudaEventDisableTiming);
        cudaEventCreateWithFlags(&ev_q,     cudaEventDisableTiming);
        cudaFuncSetAttribute(qkv_mma, cudaFuncAttributeMaxDynamicSharedMemorySize,
                             2 * BUF_BYTES);
    }

    // fork both worker streams off the capture (default) stream
    cudaEventRecord(ev_fork, 0);
    cudaStreamWaitEvent(s_kv, ev_fork, 0);
    cudaStreamWaitEvent(s_q,  ev_fork, 0);

    // branch heads (independent)
    conv_x<<<ELEMS / 4 / 256, 256, 0, s_kv>>>(X);                       // abar + zero_m
    cudaEventRecord(ev_convx, s_kv);
    conv_w<<<dim3(DMODEL * DMODEL / 4 / 256, 3), 256, 0, s_q>>>(Wq, Wk, Wv); // all 3 slabs
    cudaEventRecord(ev_convw, s_q);

    // KV branch: needs abar (own stream) + slabs 1,2 (conv_w)
    cudaStreamWaitEvent(s_kv, ev_convw, 0);
    qkv_mma<<<dim3(8, 32, 2), 256, 2 * BUF_BYTES, s_kv>>>(1, amask, bq, bk, bv); // K,V
    kv_outer<<<dim3(BATCH * NHEAD, 16), 256, 0, s_kv>>>();
    cudaEventRecord(ev_kv, s_kv);

    // Q branch: needs abar (conv_x) + slab 0 (own stream)
    cudaStreamWaitEvent(s_q, ev_convx, 0);
    qkv_mma<<<dim3(8, 32, 1), 256, 2 * BUF_BYTES, s_q>>>(0, amask, bq, bk, bv);  // Q
    cudaEventRecord(ev_q, s_q);

    // join on capture stream, final kernel
    cudaStreamWaitEvent(0, ev_kv, 0);
    cudaStreamWaitEvent(0, ev_q, 0);
    ctx_gemm<<<dim3(SEQ / 64, NHEAD, BATCH), 256>>>(out);
}

// round 12
// speedup vs baseline: 1.4528x; 1.0579x over previous
#include <cuda_runtime.h>
#include <cuda_fp16.h>
#include <cstdint>

// Problem constants
#define BATCH 2
#define SEQ   2048
#define DMODEL 1024
#define NHEAD 16
#define HDIM  64
#define ROWS  (BATCH*SEQ)          // 4096
#define ELEMS (ROWS*DMODEL)        // 4,194,304
#define KEFF  2048                 // 2-term fp16 split K

// Scratch (static __device__ globals — allocation-free per harness rules)
__device__ float g_k[ELEMS];   // masked K (K')
__device__ float g_v[ELEMS];
__device__ float g_m[BATCH*NHEAD*HDIM*HDIM];   // 131072 floats
__device__ __half g_qs[(size_t)NHEAD*ROWS*128];    // Q split [h][row][128] 16MB
__device__ __half g_abar[(size_t)ROWS*KEFF];       // [4096,2048] 16MB
__device__ __half g_bbar[(size_t)3*DMODEL*KEFF];   // 3x[1024,2048] 12MB

// ---------------------------------------------------------------------------
// Base-target (sm_80+) PTX helpers: ldmatrix / mma.sync / cp.async
// ---------------------------------------------------------------------------
__device__ __forceinline__ uint32_t smem_to_u32(const void* p) {
    uint32_t a;
    asm("{ .reg .u64 t; cvta.to.shared.u64 t, %1; cvt.u32.u64 %0, t; }" : "=r"(a) : "l"(p));
    return a;
}
__device__ __forceinline__ void ldsm_x4(uint32_t& r0, uint32_t& r1, uint32_t& r2, uint32_t& r3,
                                        uint32_t addr) {
    asm volatile("ldmatrix.sync.aligned.m8n8.x4.shared.b16 {%0,%1,%2,%3}, [%4];"
                 : "=r"(r0), "=r"(r1), "=r"(r2), "=r"(r3) : "r"(addr));
}
__device__ __forceinline__ void mma_f16(float* d, uint32_t a0, uint32_t a1, uint32_t a2,
                                        uint32_t a3, uint32_t b0, uint32_t b1) {
    asm volatile("mma.sync.aligned.m16n8k16.row.col.f32.f16.f16.f32 "
                 "{%0,%1,%2,%3}, {%4,%5,%6,%7}, {%8,%9}, {%0,%1,%2,%3};"
                 : "+f"(d[0]), "+f"(d[1]), "+f"(d[2]), "+f"(d[3])
                 : "r"(a0), "r"(a1), "r"(a2), "r"(a3), "r"(b0), "r"(b1));
}
#define CP_ASYNC16(saddr, gptr) \
    asm volatile("cp.async.cg.shared.global [%0], [%1], 16;" :: "r"(saddr), "l"(gptr))
#define CP_COMMIT() asm volatile("cp.async.commit_group;" ::: "memory")
#define CP_WAIT1()  asm volatile("cp.async.wait_group 1;" ::: "memory")
#define CP_WAIT0()  asm volatile("cp.async.wait_group 0;" ::: "memory")

// SW128 swizzle: rows of 128B, chunk16B index ^= (row & 7)
#define SWZ128(bo) ((bo) ^ (((bo) >> 3) & 0x70))

// ---------------------------------------------------------------------------
// X -> Abar = [hi | lo] along K (fp16 split). Also zeroes g_m.
// ---------------------------------------------------------------------------
__global__ __launch_bounds__(256) void conv_x(const float* __restrict__ X)
{
    if (blockIdx.x < 512) g_m[blockIdx.x * 256 + threadIdx.x] = 0.0f;

    int t = blockIdx.x * 256 + threadIdx.x;
    int idx = t * 4;
    float4 v = *(const float4*)(X + idx);
    int r = idx >> 10, k = idx & 1023;
    float f[4] = {v.x, v.y, v.z, v.w};
    __half h[4], l[4];
#pragma unroll
    for (int i = 0; i < 4; i++) {
        h[i] = __float2half(f[i]);
        l[i] = __float2half(f[i] - __half2float(h[i]));
    }
    __half* base = g_abar + (size_t)r * KEFF;
    *(__half2*)(base + k)          = __half2(h[0], h[1]);
    *(__half2*)(base + k + 2)      = __half2(h[2], h[3]);
    *(__half2*)(base + 1024 + k)   = __half2(l[0], l[1]);
    *(__half2*)(base + 1024 + k+2) = __half2(l[2], l[3]);
}

// W -> Bbar = [hi | hi]
__global__ __launch_bounds__(256) void conv_w(const float* __restrict__ Wq,
                                              const float* __restrict__ Wk,
                                              const float* __restrict__ Wv)
{
    int which = blockIdx.y;
    const float* __restrict__ W = (which == 0) ? Wq : (which == 1) ? Wk : Wv;
    int t = blockIdx.x * 256 + threadIdx.x;
    int idx = t * 4;
    float4 v = *(const float4*)(W + idx);
    int r = idx >> 10, k = idx & 1023;
    __half h[4] = {__float2half(v.x), __float2half(v.y),
                   __float2half(v.z), __float2half(v.w)};
    __half* base = g_bbar + (size_t)which * DMODEL * KEFF + (size_t)r * KEFF;
    *(__half2*)(base + k)          = __half2(h[0], h[1]);
    *(__half2*)(base + k + 2)      = __half2(h[2], h[3]);
    *(__half2*)(base + 1024 + k)   = __half2(h[0], h[1]);
    *(__half2*)(base + 1024 + k+2) = __half2(h[2], h[3]);
}

// ---------------------------------------------------------------------------
// mma.sync fp16 projection. slab 0 -> g_qs (fp16 split, +bq);
// slab 1 -> g_k (mask,+bk); slab 2 -> g_v (+bv)
// CTA 128x128, BK=64, 8 warps (2x4), warp tile 64x32, 2-stage cp.async,
// 2 CTAs/SM. dynamic smem = 64KB
// ---------------------------------------------------------------------------
#define BKC 64
#define NITER (KEFF / BKC)   // 32
#define CHUNK_BYTES 16384    // 128 rows * 128B
#define BUF_BYTES   32768    // A chunk + B chunk

__global__ __launch_bounds__(256, 2)
void qkv_mma(int zbase,
             const float* __restrict__ amask,
             const float* __restrict__ bq,
             const float* __restrict__ bk,
             const float* __restrict__ bv)
{
    extern __shared__ __align__(1024) uint8_t smem[];
    __shared__ float sBias[128];

    const int tid  = threadIdx.x;
    const int wid  = tid >> 5;
    const int lane = tid & 31;
    const int which = blockIdx.z + zbase;
    const int m0 = blockIdx.y * 128;
    const int n0 = blockIdx.x * 128;

    const float* __restrict__ bias = (which == 0) ? bq : (which == 1) ? bk : bv;
    float* __restrict__ Y          = (which == 1) ? g_k : g_v;

    const __half* __restrict__ Ag = g_abar;
    const __half* __restrict__ Bg = g_bbar + (size_t)which * DMODEL * KEFF;

    const uint32_t sbase = smem_to_u32(smem);

    if (tid < 128) sBias[tid] = bias[n0 + tid];

    const int srow = tid >> 3;        // 0..31
    const int sc   = tid & 7;         // 16B chunk within 128B row

    auto stage = [&](int buf, int it) {
        const int ke = it * BKC;
        const uint32_t abase = sbase + buf * BUF_BYTES;
        const uint32_t bbase = abase + CHUNK_BYTES;
#pragma unroll
        for (int p = 0; p < 4; p++) {
            const int row = srow + p * 32;
            const uint32_t so = SWZ128((uint32_t)(row * 128 + sc * 16));
            CP_ASYNC16(abase + so, Ag + (size_t)(m0 + row) * KEFF + ke + sc * 8);
            CP_ASYNC16(bbase + so, Bg + (size_t)(n0 + row) * KEFF + ke + sc * 8);
        }
    };

    // warp tiling: 2 warps along M, 4 along N
    const int wm0 = (wid & 1) * 64;
    const int wn0 = (wid >> 1) * 32;

    float acc[16][4];
#pragma unroll
    for (int i = 0; i < 16; i++)
#pragma unroll
        for (int j = 0; j < 4; j++) acc[i][j] = 0.0f;

    const int a_row = wm0 + (lane & 15);
    const int a_ch  = (lane >> 4);
    const int b_g   = lane >> 3;
    const int b_row = wn0 + ((b_g >> 1) << 3) + (lane & 7);
    const int b_ch  = (b_g & 1);

    stage(0, 0);
    CP_COMMIT();

    for (int it = 0; it < NITER; it++) {
        if (it + 1 < NITER) {
            stage((it + 1) & 1, it + 1);
            CP_COMMIT();
            CP_WAIT1();
        } else {
            CP_WAIT0();
        }
        __syncthreads();

        const uint32_t abase = sbase + (it & 1) * BUF_BYTES;
        const uint32_t bbase = abase + CHUNK_BYTES;

#pragma unroll
        for (int ks = 0; ks < 4; ks++) {
            uint32_t a[4][4];
#pragma unroll
            for (int mi = 0; mi < 4; mi++) {
                const int row = a_row + mi * 16;
                const int ch  = ks * 2 + a_ch;
                ldsm_x4(a[mi][0], a[mi][1], a[mi][2], a[mi][3],
                        abase + SWZ128((uint32_t)(row * 128 + ch * 16)));
            }
            uint32_t b[2][4];
#pragma unroll
            for (int np = 0; np < 2; np++) {
                const int row = b_row + np * 16;
                const int ch  = ks * 2 + b_ch;
                ldsm_x4(b[np][0], b[np][1], b[np][2], b[np][3],
                        bbase + SWZ128((uint32_t)(row * 128 + ch * 16)));
            }
#pragma unroll
            for (int mi = 0; mi < 4; mi++)
#pragma unroll
                for (int ni = 0; ni < 4; ni++) {
                    const int np = ni >> 1, hf = (ni & 1) * 2;
                    mma_f16(acc[mi * 4 + ni], a[mi][0], a[mi][1], a[mi][2], a[mi][3],
                            b[np][hf], b[np][hf + 1]);
                }
        }
        __syncthreads();
    }

    // Epilogue
    const int erow = wm0 + (lane >> 2);
    const int ecol = wn0 + (lane & 3) * 2;
#pragma unroll
    for (int mi = 0; mi < 4; mi++) {
        const int r0 = m0 + erow + mi * 16;
        const int r1 = r0 + 8;
        float mv0 = 1.0f, mv1 = 1.0f;
        if (which == 1) {
            mv0 = (amask[r0] >= 0.0f) ? 1.0f : 0.0f;
            mv1 = (amask[r1] >= 0.0f) ? 1.0f : 0.0f;
        }
#pragma unroll
        for (int ni = 0; ni < 4; ni++) {
            const int c = ecol + ni * 8;
            float v00 = acc[mi * 4 + ni][0] + sBias[c + 0];
            float v01 = acc[mi * 4 + ni][1] + sBias[c + 1];
            float v10 = acc[mi * 4 + ni][2] + sBias[c + 0];
            float v11 = acc[mi * 4 + ni][3] + sBias[c + 1];
            if (which == 0) {
                // Q: write fp16 split [hi|lo] into g_qs[h][row][128]
                const int gcol = n0 + c;
                const int hh = gcol >> 6, d = gcol & 63;
                __half h00 = __float2half(v00), h01 = __float2half(v01);
                __half h10 = __float2half(v10), h11 = __float2half(v11);
                __half l00 = __float2half(v00 - __half2float(h00));
                __half l01 = __float2half(v01 - __half2float(h01));
                __half l10 = __float2half(v10 - __half2float(h10));
                __half l11 = __float2half(v11 - __half2float(h11));
                __half* p0 = g_qs + ((size_t)hh * ROWS + r0) * 128 + d;
                __half* p1 = g_qs + ((size_t)hh * ROWS + r1) * 128 + d;
                *(__half2*)p0        = __half2(h00, h01);
                *(__half2*)(p0 + 64) = __half2(l00, l01);
                *(__half2*)p1        = __half2(h10, h11);
                *(__half2*)(p1 + 64) = __half2(l10, l11);
            } else {
                float* p0 = Y + (size_t)r0 * DMODEL + n0 + c;
                float* p1 = Y + (size_t)r1 * DMODEL + n0 + c;
                *(float2*)p0 = make_float2(v00 * mv0, v01 * mv0);
                *(float2*)p1 = make_float2(v10 * mv1, v11 * mv1);
            }
        }
    }
}

// ---------------------------------------------------------------------------
// M[b,h] += K'[b,h]^T @ V[b,h] over a 64-key slice (split-K 32 + atomics)
// grid = (32, 32), 256 threads
// ---------------------------------------------------------------------------
__global__ __launch_bounds__(256)
void kv_outer()
{
    const int bh = blockIdx.x;
    const int b = bh >> 4, h = bh & 15;
    const int kstart = blockIdx.y * 64;

    __shared__ float Ks[32][64];
    __shared__ float Vs[32][64];

    const int tid = threadIdx.x;
    const int tx = tid & 15, ty = tid >> 4;

    float acc[4][4];
#pragma unroll
    for (int i = 0; i < 4; i++)
#pragma unroll
        for (int j = 0; j < 4; j++) acc[i][j] = 0.0f;

    const int lr = tid >> 3;
    const int lc = (tid & 7) * 8;

    for (int kc = 0; kc < 2; kc++) {
        const size_t base = (size_t)(b * SEQ + kstart + kc * 32 + lr) * DMODEL + h * HDIM + lc;
        *(float4*)(&Ks[lr][lc])     = *(const float4*)(g_k + base);
        *(float4*)(&Ks[lr][lc + 4]) = *(const float4*)(g_k + base + 4);
        *(float4*)(&Vs[lr][lc])     = *(const float4*)(g_v + base);
        *(float4*)(&Vs[lr][lc + 4]) = *(const float4*)(g_v + base + 4);
        __syncthreads();

#pragma unroll
        for (int kk = 0; kk < 32; kk++) {
            const float4 a4 = *(const float4*)(&Ks[kk][ty * 4]);
            const float4 b4 = *(const float4*)(&Vs[kk][tx * 4]);
            const float a[4] = {a4.x, a4.y, a4.z, a4.w};
            const float bb[4] = {b4.x, b4.y, b4.z, b4.w};
#pragma unroll
            for (int i = 0; i < 4; i++)
#pragma unroll
                for (int j = 0; j < 4; j++)
                    acc[i][j] += a[i] * bb[j];
        }
        __syncthreads();
    }

    float* Mout = g_m + (size_t)bh * HDIM * HDIM;
#pragma unroll
    for (int i = 0; i < 4; i++)
#pragma unroll
        for (int j = 0; j < 4; j++)
            atomicAdd(&Mout[(ty * 4 + i) * HDIM + tx * 4 + j], acc[i][j]);
}

// ---------------------------------------------------------------------------
// ctx = Q @ M via mma.sync fp16: A = [Q_hi|Q_lo] (K=128), B = M_hi (reused for
// ks>=4, realizing the [hi|hi] duplication). grid (16 stile, 16 h, 2 b),
// 256 threads, 8 warps (2M x 4N), warp tile 64x16.
// dynamic smem: A 32KB @0, B 8KB @32768, Mfp32 16KB @40960 = 56KB
// ---------------------------------------------------------------------------
#define CTX_SMEM (32768 + 8192 + 16384)

__global__ __launch_bounds__(256)
void ctx_mma(float* __restrict__ out)
{
    extern __shared__ __align__(1024) uint8_t smem[];
    const uint32_t sbase = smem_to_u32(smem);
    const uint32_t sB = sbase + 32768;
    float* sM = (float*)(smem + 40960);

    const int tid  = threadIdx.x;
    const int wid  = tid >> 5;
    const int lane = tid & 31;
    const int st = blockIdx.x, h = blockIdx.y, b = blockIdx.z;
    const int s0 = st * 128;
    const size_t arow0 = (size_t)h * ROWS + b * SEQ + s0;

    // 1. stage A (Q split) via cp.async: 2 chunks of 128 rows x 128B
    {
        const int srow = tid >> 3;    // 0..31
        const int sc   = tid & 7;
#pragma unroll
        for (int c = 0; c < 2; c++)
#pragma unroll
            for (int p = 0; p < 4; p++) {
                const int row = srow + p * 32;
                CP_ASYNC16(sbase + c * 16384 + SWZ128((uint32_t)(row * 128 + sc * 16)),
                           g_qs + (arow0 + row) * 128 + c * 64 + sc * 8);
            }
        CP_COMMIT();
    }

    // 2. load M (fp32 64x64) coalesced
    {
        const float* Msrc = g_m + (size_t)(b * NHEAD + h) * HDIM * HDIM;
#pragma unroll
        for (int i = 0; i < 4; i++) {
            int idx = tid * 16 + i * 4;
            *(float4*)(sM + idx) = *(const float4*)(Msrc + idx);
        }
    }
    __syncthreads();

    // 3. transpose-convert to fp16 B[j][k] = hi(M[k][j]), swizzled
    {
        const int j  = tid >> 2;
        const int k0 = (tid & 3) * 16;
#pragma unroll
        for (int i = 0; i < 16; i++) {
            const int k = k0 + i;
            const uint32_t bo = (uint32_t)(j * 128 + k * 2);
            *(__half*)(smem + 32768 + SWZ128(bo)) = __float2half(sM[k * 64 + j]);
        }
    }
    CP_WAIT0();
    __syncthreads();

    // 4. MMA: warp tile 64 M x 16 N, K = 128 (8 k16 steps; B reused for ks>=4)
    const int wm0 = (wid & 1) * 64;
    const int wn0 = (wid >> 1) * 16;

    float acc[8][4];
#pragma unroll
    for (int i = 0; i < 8; i++)
#pragma unroll
        for (int j = 0; j < 4; j++) acc[i][j] = 0.0f;

    const int a_row = wm0 + (lane & 15);
    const int a_ch  = (lane >> 4);
    const int b_g   = lane >> 3;
    const int b_row = wn0 + ((b_g >> 1) << 3) + (lane & 7);
    const int b_ch  = (b_g & 1);

#pragma unroll
    for (int ks = 0; ks < 8; ks++) {
        const uint32_t abase = sbase + (ks >> 2) * 16384;
        const int ch_a = (ks & 3) * 2 + a_ch;
        const int ch_b = (ks & 3) * 2 + b_ch;
        uint32_t a[4][4];
#pragma unroll
        for (int mi = 0; mi < 4; mi++)
            ldsm_x4(a[mi][0], a[mi][1], a[mi][2], a[mi][3],
                    abase + SWZ128((uint32_t)((a_row + mi * 16) * 128 + ch_a * 16)));
        uint32_t bb[4];
        ldsm_x4(bb[0], bb[1], bb[2], bb[3],
                sB + SWZ128((uint32_t)(b_row * 128 + ch_b * 16)));
#pragma unroll
        for (int mi = 0; mi < 4; mi++)
#pragma unroll
            for (int ni = 0; ni < 2; ni++)
                mma_f16(acc[mi * 2 + ni], a[mi][0], a[mi][1], a[mi][2], a[mi][3],
                        bb[ni * 2], bb[ni * 2 + 1]);
    }

    // 5. epilogue
    const int erow = wm0 + (lane >> 2);
    const int ecol = wn0 + (lane & 3) * 2;
#pragma unroll
    for (int mi = 0; mi < 4; mi++) {
        const int r0 = s0 + erow + mi * 16;
        const int r1 = r0 + 8;
#pragma unroll
        for (int ni = 0; ni < 2; ni++) {
            const int c = h * HDIM + ecol + ni * 8;
            float* p0 = out + (size_t)(b * SEQ + r0) * DMODEL + c;
            float* p1 = out + (size_t)(b * SEQ + r1) * DMODEL + c;
            *(float2*)p0 = make_float2(acc[mi * 2 + ni][0], acc[mi * 2 + ni][1]);
            *(float2*)p1 = make_float2(acc[mi * 2 + ni][2], acc[mi * 2 + ni][3]);
        }
    }
}

// ---------------------------------------------------------------------------
// Launch: two-branch graph; join at ctx_mma.
// ---------------------------------------------------------------------------
extern "C" void kernel_launch(void* const* d_in, const int* in_sizes, int n_in,
                              void* d_out, int out_size)
{
    const float* X     = (const float*)d_in[0];
    const float* amask = (const float*)d_in[1];
    const float* Wq    = (const float*)d_in[2];
    const float* bq    = (const float*)d_in[3];
    const float* Wk    = (const float*)d_in[4];
    const float* bk    = (const float*)d_in[5];
    const float* Wv    = (const float*)d_in[6];
    const float* bv    = (const float*)d_in[7];
    float* out = (float*)d_out;

    static cudaStream_t s_kv = nullptr, s_q = nullptr;
    static cudaEvent_t ev_fork = nullptr, ev_convx = nullptr, ev_convw = nullptr,
                       ev_kv = nullptr, ev_q = nullptr;
    if (s_kv == nullptr) {
        cudaStreamCreateWithFlags(&s_kv, cudaStreamNonBlocking);
        cudaStreamCreateWithFlags(&s_q,  cudaStreamNonBlocking);
        cudaEventCreateWithFlags(&ev_fork,  cudaEventDisableTiming);
        cudaEventCreateWithFlags(&ev_convx, cudaEventDisableTiming);
        cudaEventCreateWithFlags(&ev_convw, cudaEventDisableTiming);
        cudaEventCreateWithFlags(&ev_kv,    cudaEventDisableTiming);
        cudaEventCreateWithFlags(&ev_q,     cudaEventDisableTiming);
        cudaFuncSetAttribute(qkv_mma, cudaFuncAttributeMaxDynamicSharedMemorySize,
                             2 * BUF_BYTES);
        cudaFuncSetAttribute(ctx_mma, cudaFuncAttributeMaxDynamicSharedMemorySize,
                             CTX_SMEM);
    }

    // fork both worker streams off the capture (default) stream
    cudaEventRecord(ev_fork, 0);
    cudaStreamWaitEvent(s_kv, ev_fork, 0);
    cudaStreamWaitEvent(s_q,  ev_fork, 0);

    // branch heads (independent)
    conv_x<<<ELEMS / 4 / 256, 256, 0, s_kv>>>(X);                       // abar + zero_m
    cudaEventRecord(ev_convx, s_kv);
    conv_w<<<dim3(DMODEL * DMODEL / 4 / 256, 3), 256, 0, s_q>>>(Wq, Wk, Wv);
    cudaEventRecord(ev_convw, s_q);

    // KV branch: needs abar (own stream) + slabs 1,2 (conv_w)
    cudaStreamWaitEvent(s_kv, ev_convw, 0);
    qkv_mma<<<dim3(8, 32, 2), 256, 2 * BUF_BYTES, s_kv>>>(1, amask, bq, bk, bv); // K,V
    kv_outer<<<dim3(BATCH * NHEAD, 32), 256, 0, s_kv>>>();
    cudaEventRecord(ev_kv, s_kv);

    // Q branch: needs abar (conv_x) + slab 0 (own stream)
    cudaStreamWaitEvent(s_q, ev_convx, 0);
    qkv_mma<<<dim3(8, 32, 1), 256, 2 * BUF_BYTES, s_q>>>(0, amask, bq, bk, bv);  // Q
    cudaEventRecord(ev_q, s_q);

    // join on capture stream, final kernel
    cudaStreamWaitEvent(0, ev_kv, 0);
    cudaStreamWaitEvent(0, ev_q, 0);
    ctx_mma<<<dim3(SEQ / 128, NHEAD, BATCH), 256, CTX_SMEM>>>(out);
}

// round 13
// speedup vs baseline: 2.0062x; 1.3810x over previous
#include <cuda_runtime.h>
#include <cuda_fp16.h>
#include <cstdint>

// Problem constants
#define BATCH 2
#define SEQ   2048
#define DMODEL 1024
#define NHEAD 16
#define HDIM  64
#define ROWS  (BATCH*SEQ)          // 4096
#define ELEMS (ROWS*DMODEL)        // 4,194,304
#define KEFF  2048                 // 2-term fp16 split K

// Scratch (static __device__ globals — allocation-free per harness rules)
__device__ float g_k[ELEMS];   // masked K (K')
__device__ float g_v[ELEMS];
__device__ float g_m[BATCH*NHEAD*HDIM*HDIM];   // 131072 floats
__device__ __half g_qs[(size_t)NHEAD*ROWS*128];    // Q split [h][row][128] 16MB
__device__ __half g_abar[(size_t)ROWS*KEFF];       // [4096,2048] 16MB
__device__ __half g_bbar[(size_t)3*DMODEL*KEFF];   // 3x[1024,2048] 12MB

// ---------------------------------------------------------------------------
// Base-target (sm_80+) PTX helpers: ldmatrix / mma.sync / cp.async
// ---------------------------------------------------------------------------
__device__ __forceinline__ uint32_t smem_to_u32(const void* p) {
    uint32_t a;
    asm("{ .reg .u64 t; cvta.to.shared.u64 t, %1; cvt.u32.u64 %0, t; }" : "=r"(a) : "l"(p));
    return a;
}
__device__ __forceinline__ void ldsm_x4(uint32_t& r0, uint32_t& r1, uint32_t& r2, uint32_t& r3,
                                        uint32_t addr) {
    asm volatile("ldmatrix.sync.aligned.m8n8.x4.shared.b16 {%0,%1,%2,%3}, [%4];"
                 : "=r"(r0), "=r"(r1), "=r"(r2), "=r"(r3) : "r"(addr));
}
__device__ __forceinline__ void mma_f16(float* d, uint32_t a0, uint32_t a1, uint32_t a2,
                                        uint32_t a3, uint32_t b0, uint32_t b1) {
    asm volatile("mma.sync.aligned.m16n8k16.row.col.f32.f16.f16.f32 "
                 "{%0,%1,%2,%3}, {%4,%5,%6,%7}, {%8,%9}, {%0,%1,%2,%3};"
                 : "+f"(d[0]), "+f"(d[1]), "+f"(d[2]), "+f"(d[3])
                 : "r"(a0), "r"(a1), "r"(a2), "r"(a3), "r"(b0), "r"(b1));
}
#define CP_ASYNC16(saddr, gptr) \
    asm volatile("cp.async.cg.shared.global [%0], [%1], 16;" :: "r"(saddr), "l"(gptr))
#define CP_COMMIT() asm volatile("cp.async.commit_group;" ::: "memory")
#define CP_WAIT1()  asm volatile("cp.async.wait_group 1;" ::: "memory")
#define CP_WAIT0()  asm volatile("cp.async.wait_group 0;" ::: "memory")

// SW128 swizzle: rows of 128B, chunk16B index ^= (row & 7)
#define SWZ128(bo) ((bo) ^ (((bo) >> 3) & 0x70))

// ---------------------------------------------------------------------------
// X -> Abar = [hi | lo] along K (fp16 split). Also zeroes g_m.
// ---------------------------------------------------------------------------
__global__ __launch_bounds__(256) void conv_x(const float* __restrict__ X)
{
    if (blockIdx.x < 512) g_m[blockIdx.x * 256 + threadIdx.x] = 0.0f;

    int t = blockIdx.x * 256 + threadIdx.x;
    int idx = t * 4;
    float4 v = *(const float4*)(X + idx);
    int r = idx >> 10, k = idx & 1023;
    float f[4] = {v.x, v.y, v.z, v.w};
    __half h[4], l[4];
#pragma unroll
    for (int i = 0; i < 4; i++) {
        h[i] = __float2half(f[i]);
        l[i] = __float2half(f[i] - __half2float(h[i]));
    }
    __half* base = g_abar + (size_t)r * KEFF;
    *(__half2*)(base + k)          = __half2(h[0], h[1]);
    *(__half2*)(base + k + 2)      = __half2(h[2], h[3]);
    *(__half2*)(base + 1024 + k)   = __half2(l[0], l[1]);
    *(__half2*)(base + 1024 + k+2) = __half2(l[2], l[3]);
}

// W -> Bbar = [hi | hi]
__global__ __launch_bounds__(256) void conv_w(const float* __restrict__ Wq,
                                              const float* __restrict__ Wk,
                                              const float* __restrict__ Wv)
{
    int which = blockIdx.y;
    const float* __restrict__ W = (which == 0) ? Wq : (which == 1) ? Wk : Wv;
    int t = blockIdx.x * 256 + threadIdx.x;
    int idx = t * 4;
    float4 v = *(const float4*)(W + idx);
    int r = idx >> 10, k = idx & 1023;
    __half h[4] = {__float2half(v.x), __float2half(v.y),
                   __float2half(v.z), __float2half(v.w)};
    __half* base = g_bbar + (size_t)which * DMODEL * KEFF + (size_t)r * KEFF;
    *(__half2*)(base + k)          = __half2(h[0], h[1]);
    *(__half2*)(base + k + 2)      = __half2(h[2], h[3]);
    *(__half2*)(base + 1024 + k)   = __half2(h[0], h[1]);
    *(__half2*)(base + 1024 + k+2) = __half2(h[2], h[3]);
}

// ---------------------------------------------------------------------------
// mma.sync fp16 projection, templated on k-iteration count:
//   NIT=32: full [hi|lo]x[hi|hi] split (exact X);  NIT=16: hi*hi only.
// slab 0 -> g_qs (fp16 split, +bq); slab 1 -> g_k (mask,+bk); slab 2 -> g_v (+bv)
// CTA 128x128, BK=64, 8 warps (2x4), warp tile 64x32, 2-stage cp.async,
// 2 CTAs/SM. dynamic smem = 64KB
// ---------------------------------------------------------------------------
#define BKC 64
#define CHUNK_BYTES 16384    // 128 rows * 128B
#define BUF_BYTES   32768    // A chunk + B chunk

template<int NIT>
__global__ __launch_bounds__(256, 2)
void qkv_mma(int zbase,
             const float* __restrict__ amask,
             const float* __restrict__ bq,
             const float* __restrict__ bk,
             const float* __restrict__ bv)
{
    extern __shared__ __align__(1024) uint8_t smem[];
    __shared__ float sBias[128];

    const int tid  = threadIdx.x;
    const int wid  = tid >> 5;
    const int lane = tid & 31;
    const int which = blockIdx.z + zbase;
    const int m0 = blockIdx.y * 128;
    const int n0 = blockIdx.x * 128;

    const float* __restrict__ bias = (which == 0) ? bq : (which == 1) ? bk : bv;
    float* __restrict__ Y          = (which == 1) ? g_k : g_v;

    const __half* __restrict__ Ag = g_abar;
    const __half* __restrict__ Bg = g_bbar + (size_t)which * DMODEL * KEFF;

    const uint32_t sbase = smem_to_u32(smem);

    if (tid < 128) sBias[tid] = bias[n0 + tid];

    const int srow = tid >> 3;        // 0..31
    const int sc   = tid & 7;         // 16B chunk within 128B row

    auto stage = [&](int buf, int it) {
        const int ke = it * BKC;
        const uint32_t abase = sbase + buf * BUF_BYTES;
        const uint32_t bbase = abase + CHUNK_BYTES;
#pragma unroll
        for (int p = 0; p < 4; p++) {
            const int row = srow + p * 32;
            const uint32_t so = SWZ128((uint32_t)(row * 128 + sc * 16));
            CP_ASYNC16(abase + so, Ag + (size_t)(m0 + row) * KEFF + ke + sc * 8);
            CP_ASYNC16(bbase + so, Bg + (size_t)(n0 + row) * KEFF + ke + sc * 8);
        }
    };

    // warp tiling: 2 warps along M, 4 along N
    const int wm0 = (wid & 1) * 64;
    const int wn0 = (wid >> 1) * 32;

    float acc[16][4];
#pragma unroll
    for (int i = 0; i < 16; i++)
#pragma unroll
        for (int j = 0; j < 4; j++) acc[i][j] = 0.0f;

    const int a_row = wm0 + (lane & 15);
    const int a_ch  = (lane >> 4);
    const int b_g   = lane >> 3;
    const int b_row = wn0 + ((b_g >> 1) << 3) + (lane & 7);
    const int b_ch  = (b_g & 1);

    stage(0, 0);
    CP_COMMIT();

    for (int it = 0; it < NIT; it++) {
        if (it + 1 < NIT) {
            stage((it + 1) & 1, it + 1);
            CP_COMMIT();
            CP_WAIT1();
        } else {
            CP_WAIT0();
        }
        __syncthreads();

        const uint32_t abase = sbase + (it & 1) * BUF_BYTES;
        const uint32_t bbase = abase + CHUNK_BYTES;

#pragma unroll
        for (int ks = 0; ks < 4; ks++) {
            uint32_t a[4][4];
#pragma unroll
            for (int mi = 0; mi < 4; mi++) {
                const int row = a_row + mi * 16;
                const int ch  = ks * 2 + a_ch;
                ldsm_x4(a[mi][0], a[mi][1], a[mi][2], a[mi][3],
                        abase + SWZ128((uint32_t)(row * 128 + ch * 16)));
            }
            uint32_t b[2][4];
#pragma unroll
            for (int np = 0; np < 2; np++) {
                const int row = b_row + np * 16;
                const int ch  = ks * 2 + b_ch;
                ldsm_x4(b[np][0], b[np][1], b[np][2], b[np][3],
                        bbase + SWZ128((uint32_t)(row * 128 + ch * 16)));
            }
#pragma unroll
            for (int mi = 0; mi < 4; mi++)
#pragma unroll
                for (int ni = 0; ni < 4; ni++) {
                    const int np = ni >> 1, hf = (ni & 1) * 2;
                    mma_f16(acc[mi * 4 + ni], a[mi][0], a[mi][1], a[mi][2], a[mi][3],
                            b[np][hf], b[np][hf + 1]);
                }
        }
        __syncthreads();
    }

    // Epilogue
    const int erow = wm0 + (lane >> 2);
    const int ecol = wn0 + (lane & 3) * 2;
#pragma unroll
    for (int mi = 0; mi < 4; mi++) {
        const int r0 = m0 + erow + mi * 16;
        const int r1 = r0 + 8;
        float mv0 = 1.0f, mv1 = 1.0f;
        if (which == 1) {
            mv0 = (amask[r0] >= 0.0f) ? 1.0f : 0.0f;
            mv1 = (amask[r1] >= 0.0f) ? 1.0f : 0.0f;
        }
#pragma unroll
        for (int ni = 0; ni < 4; ni++) {
            const int c = ecol + ni * 8;
            float v00 = acc[mi * 4 + ni][0] + sBias[c + 0];
            float v01 = acc[mi * 4 + ni][1] + sBias[c + 1];
            float v10 = acc[mi * 4 + ni][2] + sBias[c + 0];
            float v11 = acc[mi * 4 + ni][3] + sBias[c + 1];
            if (which == 0) {
                // Q: write fp16 split [hi|lo] into g_qs[h][row][128]
                const int gcol = n0 + c;
                const int hh = gcol >> 6, d = gcol & 63;
                __half h00 = __float2half(v00), h01 = __float2half(v01);
                __half h10 = __float2half(v10), h11 = __float2half(v11);
                __half l00 = __float2half(v00 - __half2float(h00));
                __half l01 = __float2half(v01 - __half2float(h01));
                __half l10 = __float2half(v10 - __half2float(h10));
                __half l11 = __float2half(v11 - __half2float(h11));
                __half* p0 = g_qs + ((size_t)hh * ROWS + r0) * 128 + d;
                __half* p1 = g_qs + ((size_t)hh * ROWS + r1) * 128 + d;
                *(__half2*)p0        = __half2(h00, h01);
                *(__half2*)(p0 + 64) = __half2(l00, l01);
                *(__half2*)p1        = __half2(h10, h11);
                *(__half2*)(p1 + 64) = __half2(l10, l11);
            } else {
                float* p0 = Y + (size_t)r0 * DMODEL + n0 + c;
                float* p1 = Y + (size_t)r1 * DMODEL + n0 + c;
                *(float2*)p0 = make_float2(v00 * mv0, v01 * mv0);
                *(float2*)p1 = make_float2(v10 * mv1, v11 * mv1);
            }
        }
    }
}

// ---------------------------------------------------------------------------
// M[b,h] += K'[b,h]^T @ V[b,h] over a 64-key slice (split-K 32 + atomics)
// grid = (32, 32), 256 threads
// ---------------------------------------------------------------------------
__global__ __launch_bounds__(256)
void kv_outer()
{
    const int bh = blockIdx.x;
    const int b = bh >> 4, h = bh & 15;
    const int kstart = blockIdx.y * 64;

    __shared__ float Ks[32][64];
    __shared__ float Vs[32][64];

    const int tid = threadIdx.x;
    const int tx = tid & 15, ty = tid >> 4;

    float acc[4][4];
#pragma unroll
    for (int i = 0; i < 4; i++)
#pragma unroll
        for (int j = 0; j < 4; j++) acc[i][j] = 0.0f;

    const int lr = tid >> 3;
    const int lc = (tid & 7) * 8;

    for (int kc = 0; kc < 2; kc++) {
        const size_t base = (size_t)(b * SEQ + kstart + kc * 32 + lr) * DMODEL + h * HDIM + lc;
        *(float4*)(&Ks[lr][lc])     = *(const float4*)(g_k + base);
        *(float4*)(&Ks[lr][lc + 4]) = *(const float4*)(g_k + base + 4);
        *(float4*)(&Vs[lr][lc])     = *(const float4*)(g_v + base);
        *(float4*)(&Vs[lr][lc + 4]) = *(const float4*)(g_v + base + 4);
        __syncthreads();

#pragma unroll
        for (int kk = 0; kk < 32; kk++) {
            const float4 a4 = *(const float4*)(&Ks[kk][ty * 4]);
            const float4 b4 = *(const float4*)(&Vs[kk][tx * 4]);
            const float a[4] = {a4.x, a4.y, a4.z, a4.w};
            const float bb[4] = {b4.x, b4.y, b4.z, b4.w};
#pragma unroll
            for (int i = 0; i < 4; i++)
#pragma unroll
                for (int j = 0; j < 4; j++)
                    acc[i][j] += a[i] * bb[j];
        }
        __syncthreads();
    }

    float* Mout = g_m + (size_t)bh * HDIM * HDIM;
#pragma unroll
    for (int i = 0; i < 4; i++)
#pragma unroll
        for (int j = 0; j < 4; j++)
            atomicAdd(&Mout[(ty * 4 + i) * HDIM + tx * 4 + j], acc[i][j]);
}

// ---------------------------------------------------------------------------
// ctx = Q @ M via mma.sync fp16: A = [Q_hi|Q_lo] (K=128), B = M_hi (reused for
// ks>=4). grid (16 stile, 16 h, 2 b), 256 threads, 8 warps (2M x 4N).
// dynamic smem: A 32KB @0, B 8KB @32768, Mfp32 16KB @40960 = 56KB
// ---------------------------------------------------------------------------
#define CTX_SMEM (32768 + 8192 + 16384)

__global__ __launch_bounds__(256)
void ctx_mma(float* __restrict__ out)
{
    extern __shared__ __align__(1024) uint8_t smem[];
    const uint32_t sbase = smem_to_u32(smem);
    const uint32_t sB = sbase + 32768;
    float* sM = (float*)(smem + 40960);

    const int tid  = threadIdx.x;
    const int wid  = tid >> 5;
    const int lane = tid & 31;
    const int st = blockIdx.x, h = blockIdx.y, b = blockIdx.z;
    const int s0 = st * 128;
    const size_t arow0 = (size_t)h * ROWS + b * SEQ + s0;

    // 1. stage A (Q split) via cp.async
    {
        const int srow = tid >> 3;    // 0..31
        const int sc   = tid & 7;
#pragma unroll
        for (int c = 0; c < 2; c++)
#pragma unroll
            for (int p = 0; p < 4; p++) {
                const int row = srow + p * 32;
                CP_ASYNC16(sbase + c * 16384 + SWZ128((uint32_t)(row * 128 + sc * 16)),
                           g_qs + (arow0 + row) * 128 + c * 64 + sc * 8);
            }
        CP_COMMIT();
    }

    // 2. load M (fp32 64x64) coalesced
    {
        const float* Msrc = g_m + (size_t)(b * NHEAD + h) * HDIM * HDIM;
#pragma unroll
        for (int i = 0; i < 4; i++) {
            int idx = tid * 16 + i * 4;
            *(float4*)(sM + idx) = *(const float4*)(Msrc + idx);
        }
    }
    __syncthreads();

    // 3. transpose-convert to fp16 B[j][k] = hi(M[k][j]), swizzled
    {
        const int j  = tid >> 2;
        const int k0 = (tid & 3) * 16;
#pragma unroll
        for (int i = 0; i < 16; i++) {
            const int k = k0 + i;
            const uint32_t bo = (uint32_t)(j * 128 + k * 2);
            *(__half*)(smem + 32768 + SWZ128(bo)) = __float2half(sM[k * 64 + j]);
        }
    }
    CP_WAIT0();
    __syncthreads();

    // 4. MMA: warp tile 64 M x 16 N, K = 128 (8 k16 steps; B reused for ks>=4)
    const int wm0 = (wid & 1) * 64;
    const int wn0 = (wid >> 1) * 16;

    float acc[8][4];
#pragma unroll
    for (int i = 0; i < 8; i++)
#pragma unroll
        for (int j = 0; j < 4; j++) acc[i][j] = 0.0f;

    const int a_row = wm0 + (lane & 15);
    const int a_ch  = (lane >> 4);
    const int b_g   = lane >> 3;
    const int b_row = wn0 + ((b_g >> 1) << 3) + (lane & 7);
    const int b_ch  = (b_g & 1);

#pragma unroll
    for (int ks = 0; ks < 8; ks++) {
        const uint32_t abase = sbase + (ks >> 2) * 16384;
        const int ch_a = (ks & 3) * 2 + a_ch;
        const int ch_b = (ks & 3) * 2 + b_ch;
        uint32_t a[4][4];
#pragma unroll
        for (int mi = 0; mi < 4; mi++)
            ldsm_x4(a[mi][0], a[mi][1], a[mi][2], a[mi][3],
                    abase + SWZ128((uint32_t)((a_row + mi * 16) * 128 + ch_a * 16)));
        uint32_t bb[4];
        ldsm_x4(bb[0], bb[1], bb[2], bb[3],
                sB + SWZ128((uint32_t)(b_row * 128 + ch_b * 16)));
#pragma unroll
        for (int mi = 0; mi < 4; mi++)
#pragma unroll
            for (int ni = 0; ni < 2; ni++)
                mma_f16(acc[mi * 2 + ni], a[mi][0], a[mi][1], a[mi][2], a[mi][3],
                        bb[ni * 2], bb[ni * 2 + 1]);
    }

    // 5. epilogue
    const int erow = wm0 + (lane >> 2);
    const int ecol = wn0 + (lane & 3) * 2;
#pragma unroll
    for (int mi = 0; mi < 4; mi++) {
        const int r0 = s0 + erow + mi * 16;
        const int r1 = r0 + 8;
#pragma unroll
        for (int ni = 0; ni < 2; ni++) {
            const int c = h * HDIM + ecol + ni * 8;
            float* p0 = out + (size_t)(b * SEQ + r0) * DMODEL + c;
            float* p1 = out + (size_t)(b * SEQ + r1) * DMODEL + c;
            *(float2*)p0 = make_float2(acc[mi * 2 + ni][0], acc[mi * 2 + ni][1]);
            *(float2*)p1 = make_float2(acc[mi * 2 + ni][2], acc[mi * 2 + ni][3]);
        }
    }
}

// ---------------------------------------------------------------------------
// Launch: two-branch graph; join at ctx_mma.
// ---------------------------------------------------------------------------
extern "C" void kernel_launch(void* const* d_in, const int* in_sizes, int n_in,
                              void* d_out, int out_size)
{
    const float* X     = (const float*)d_in[0];
    const float* amask = (const float*)d_in[1];
    const float* Wq    = (const float*)d_in[2];
    const float* bq    = (const float*)d_in[3];
    const float* Wk    = (const float*)d_in[4];
    const float* bk    = (const float*)d_in[5];
    const float* Wv    = (const float*)d_in[6];
    const float* bv    = (const float*)d_in[7];
    float* out = (float*)d_out;

    static cudaStream_t s_kv = nullptr, s_q = nullptr;
    static cudaEvent_t ev_fork = nullptr, ev_convx = nullptr, ev_convw = nullptr,
                       ev_kv = nullptr, ev_q = nullptr;
    if (s_kv == nullptr) {
        cudaStreamCreateWithFlags(&s_kv, cudaStreamNonBlocking);
        cudaStreamCreateWithFlags(&s_q,  cudaStreamNonBlocking);
        cudaEventCreateWithFlags(&ev_fork,  cudaEventDisableTiming);
        cudaEventCreateWithFlags(&ev_convx, cudaEventDisableTiming);
        cudaEventCreateWithFlags(&ev_convw, cudaEventDisableTiming);
        cudaEventCreateWithFlags(&ev_kv,    cudaEventDisableTiming);
        cudaEventCreateWithFlags(&ev_q,     cudaEventDisableTiming);
        cudaFuncSetAttribute(qkv_mma<16>, cudaFuncAttributeMaxDynamicSharedMemorySize,
                             2 * BUF_BYTES);
        cudaFuncSetAttribute(qkv_mma<32>, cudaFuncAttributeMaxDynamicSharedMemorySize,
                             2 * BUF_BYTES);
        cudaFuncSetAttribute(ctx_mma, cudaFuncAttributeMaxDynamicSharedMemorySize,
                             CTX_SMEM);
    }

    // fork both worker streams off the capture (default) stream
    cudaEventRecord(ev_fork, 0);
    cudaStreamWaitEvent(s_kv, ev_fork, 0);
    cudaStreamWaitEvent(s_q,  ev_fork, 0);

    // branch heads (independent)
    conv_x<<<ELEMS / 4 / 256, 256, 0, s_kv>>>(X);                       // abar + zero_m
    cudaEventRecord(ev_convx, s_kv);
    conv_w<<<dim3(DMODEL * DMODEL / 4 / 256, 3), 256, 0, s_q>>>(Wq, Wk, Wv);
    cudaEventRecord(ev_convw, s_q);

    // KV branch: hi*hi only (NIT=16)
    cudaStreamWaitEvent(s_kv, ev_convw, 0);
    qkv_mma<16><<<dim3(8, 32, 2), 256, 2 * BUF_BYTES, s_kv>>>(1, amask, bq, bk, bv); // K,V
    kv_outer<<<dim3(BATCH * NHEAD, 32), 256, 0, s_kv>>>();
    cudaEventRecord(ev_kv, s_kv);

    // Q branch: full split (NIT=32)
    cudaStreamWaitEvent(s_q, ev_convx, 0);
    qkv_mma<32><<<dim3(8, 32, 1), 256, 2 * BUF_BYTES, s_q>>>(0, amask, bq, bk, bv);  // Q
    cudaEventRecord(ev_q, s_q);

    // join on capture stream, final kernel
    cudaStreamWaitEvent(0, ev_kv, 0);
    cudaStreamWaitEvent(0, ev_q, 0);
    ctx_mma<<<dim3(SEQ / 128, NHEAD, BATCH), 256, CTX_SMEM>>>(out);
}

// round 14
// speedup vs baseline: 2.2870x; 1.1399x over previous
#include <cuda_runtime.h>
#include <cuda_fp16.h>
#include <cstdint>

// Problem constants
#define BATCH 2
#define SEQ   2048
#define DMODEL 1024
#define NHEAD 16
#define HDIM  64
#define ROWS  (BATCH*SEQ)          // 4096
#define ELEMS (ROWS*DMODEL)        // 4,194,304
#define KEFF  1024                 // hi-only fp16, K = DMODEL

// Scratch (static __device__ globals — allocation-free per harness rules)
__device__ float g_k[ELEMS];   // masked K (K')
__device__ float g_v[ELEMS];
__device__ float g_m[BATCH*NHEAD*HDIM*HDIM];   // 131072 floats
__device__ __half g_qs[(size_t)NHEAD*ROWS*64];     // Q_hi [h][row][64] 8MB
__device__ __half g_abar[(size_t)ROWS*KEFF];       // X_hi [4096,1024] 8MB
__device__ __half g_bbar[(size_t)3*DMODEL*KEFF];   // W_hi 3x[1024,1024] 6MB

// ---------------------------------------------------------------------------
// Base-target (sm_80+) PTX helpers: ldmatrix / mma.sync / cp.async
// ---------------------------------------------------------------------------
__device__ __forceinline__ uint32_t smem_to_u32(const void* p) {
    uint32_t a;
    asm("{ .reg .u64 t; cvta.to.shared.u64 t, %1; cvt.u32.u64 %0, t; }" : "=r"(a) : "l"(p));
    return a;
}
__device__ __forceinline__ void ldsm_x4(uint32_t& r0, uint32_t& r1, uint32_t& r2, uint32_t& r3,
                                        uint32_t addr) {
    asm volatile("ldmatrix.sync.aligned.m8n8.x4.shared.b16 {%0,%1,%2,%3}, [%4];"
                 : "=r"(r0), "=r"(r1), "=r"(r2), "=r"(r3) : "r"(addr));
}
__device__ __forceinline__ void mma_f16(float* d, uint32_t a0, uint32_t a1, uint32_t a2,
                                        uint32_t a3, uint32_t b0, uint32_t b1) {
    asm volatile("mma.sync.aligned.m16n8k16.row.col.f32.f16.f16.f32 "
                 "{%0,%1,%2,%3}, {%4,%5,%6,%7}, {%8,%9}, {%0,%1,%2,%3};"
                 : "+f"(d[0]), "+f"(d[1]), "+f"(d[2]), "+f"(d[3])
                 : "r"(a0), "r"(a1), "r"(a2), "r"(a3), "r"(b0), "r"(b1));
}
#define CP_ASYNC16(saddr, gptr) \
    asm volatile("cp.async.cg.shared.global [%0], [%1], 16;" :: "r"(saddr), "l"(gptr))
#define CP_COMMIT() asm volatile("cp.async.commit_group;" ::: "memory")
#define CP_WAIT1()  asm volatile("cp.async.wait_group 1;" ::: "memory")
#define CP_WAIT0()  asm volatile("cp.async.wait_group 0;" ::: "memory")

// SW128 swizzle: rows of 128B, chunk16B index ^= (row & 7)
#define SWZ128(bo) ((bo) ^ (((bo) >> 3) & 0x70))

// ---------------------------------------------------------------------------
// X -> X_hi (fp16). Also zeroes g_m.
// ---------------------------------------------------------------------------
__global__ __launch_bounds__(256) void conv_x(const float* __restrict__ X)
{
    if (blockIdx.x < 512) g_m[blockIdx.x * 256 + threadIdx.x] = 0.0f;

    int t = blockIdx.x * 256 + threadIdx.x;
    int idx = t * 4;
    float4 v = *(const float4*)(X + idx);
    __half* base = g_abar + idx;
    *(__half2*)(base)     = __half2(__float2half(v.x), __float2half(v.y));
    *(__half2*)(base + 2) = __half2(__float2half(v.z), __float2half(v.w));
}

// W -> W_hi (fp16), 3 slabs
__global__ __launch_bounds__(256) void conv_w(const float* __restrict__ Wq,
                                              const float* __restrict__ Wk,
                                              const float* __restrict__ Wv)
{
    int which = blockIdx.y;
    const float* __restrict__ W = (which == 0) ? Wq : (which == 1) ? Wk : Wv;
    int t = blockIdx.x * 256 + threadIdx.x;
    int idx = t * 4;
    float4 v = *(const float4*)(W + idx);
    __half* base = g_bbar + (size_t)which * DMODEL * KEFF + idx;
    *(__half2*)(base)     = __half2(__float2half(v.x), __float2half(v.y));
    *(__half2*)(base + 2) = __half2(__float2half(v.z), __float2half(v.w));
}

// ---------------------------------------------------------------------------
// mma.sync fp16 projection (hi*hi, K=1024, NIT=16).
// slab 0 -> g_qs (fp16 hi, +bq); slab 1 -> g_k (mask,+bk); slab 2 -> g_v (+bv)
// CTA 128x128, BK=64, 8 warps (2x4), warp tile 64x32, 2-stage cp.async,
// 2 CTAs/SM. dynamic smem = 64KB
// ---------------------------------------------------------------------------
#define BKC 64
#define NITER (KEFF / BKC)   // 16
#define CHUNK_BYTES 16384    // 128 rows * 128B
#define BUF_BYTES   32768    // A chunk + B chunk

__global__ __launch_bounds__(256, 2)
void qkv_mma(int zbase,
             const float* __restrict__ amask,
             const float* __restrict__ bq,
             const float* __restrict__ bk,
             const float* __restrict__ bv)
{
    extern __shared__ __align__(1024) uint8_t smem[];
    __shared__ float sBias[128];

    const int tid  = threadIdx.x;
    const int wid  = tid >> 5;
    const int lane = tid & 31;
    const int which = blockIdx.z + zbase;
    const int m0 = blockIdx.y * 128;
    const int n0 = blockIdx.x * 128;

    const float* __restrict__ bias = (which == 0) ? bq : (which == 1) ? bk : bv;
    float* __restrict__ Y          = (which == 1) ? g_k : g_v;

    const __half* __restrict__ Ag = g_abar;
    const __half* __restrict__ Bg = g_bbar + (size_t)which * DMODEL * KEFF;

    const uint32_t sbase = smem_to_u32(smem);

    if (tid < 128) sBias[tid] = bias[n0 + tid];

    const int srow = tid >> 3;        // 0..31
    const int sc   = tid & 7;         // 16B chunk within 128B row

    auto stage = [&](int buf, int it) {
        const int ke = it * BKC;
        const uint32_t abase = sbase + buf * BUF_BYTES;
        const uint32_t bbase = abase + CHUNK_BYTES;
#pragma unroll
        for (int p = 0; p < 4; p++) {
            const int row = srow + p * 32;
            const uint32_t so = SWZ128((uint32_t)(row * 128 + sc * 16));
            CP_ASYNC16(abase + so, Ag + (size_t)(m0 + row) * KEFF + ke + sc * 8);
            CP_ASYNC16(bbase + so, Bg + (size_t)(n0 + row) * KEFF + ke + sc * 8);
        }
    };

    // warp tiling: 2 warps along M, 4 along N
    const int wm0 = (wid & 1) * 64;
    const int wn0 = (wid >> 1) * 32;

    float acc[16][4];
#pragma unroll
    for (int i = 0; i < 16; i++)
#pragma unroll
        for (int j = 0; j < 4; j++) acc[i][j] = 0.0f;

    const int a_row = wm0 + (lane & 15);
    const int a_ch  = (lane >> 4);
    const int b_g   = lane >> 3;
    const int b_row = wn0 + ((b_g >> 1) << 3) + (lane & 7);
    const int b_ch  = (b_g & 1);

    stage(0, 0);
    CP_COMMIT();

    for (int it = 0; it < NITER; it++) {
        if (it + 1 < NITER) {
            stage((it + 1) & 1, it + 1);
            CP_COMMIT();
            CP_WAIT1();
        } else {
            CP_WAIT0();
        }
        __syncthreads();

        const uint32_t abase = sbase + (it & 1) * BUF_BYTES;
        const uint32_t bbase = abase + CHUNK_BYTES;

#pragma unroll
        for (int ks = 0; ks < 4; ks++) {
            uint32_t a[4][4];
#pragma unroll
            for (int mi = 0; mi < 4; mi++) {
                const int row = a_row + mi * 16;
                const int ch  = ks * 2 + a_ch;
                ldsm_x4(a[mi][0], a[mi][1], a[mi][2], a[mi][3],
                        abase + SWZ128((uint32_t)(row * 128 + ch * 16)));
            }
            uint32_t b[2][4];
#pragma unroll
            for (int np = 0; np < 2; np++) {
                const int row = b_row + np * 16;
                const int ch  = ks * 2 + b_ch;
                ldsm_x4(b[np][0], b[np][1], b[np][2], b[np][3],
                        bbase + SWZ128((uint32_t)(row * 128 + ch * 16)));
            }
#pragma unroll
            for (int mi = 0; mi < 4; mi++)
#pragma unroll
                for (int ni = 0; ni < 4; ni++) {
                    const int np = ni >> 1, hf = (ni & 1) * 2;
                    mma_f16(acc[mi * 4 + ni], a[mi][0], a[mi][1], a[mi][2], a[mi][3],
                            b[np][hf], b[np][hf + 1]);
                }
        }
        __syncthreads();
    }

    // Epilogue
    const int erow = wm0 + (lane >> 2);
    const int ecol = wn0 + (lane & 3) * 2;
#pragma unroll
    for (int mi = 0; mi < 4; mi++) {
        const int r0 = m0 + erow + mi * 16;
        const int r1 = r0 + 8;
        float mv0 = 1.0f, mv1 = 1.0f;
        if (which == 1) {
            mv0 = (amask[r0] >= 0.0f) ? 1.0f : 0.0f;
            mv1 = (amask[r1] >= 0.0f) ? 1.0f : 0.0f;
        }
#pragma unroll
        for (int ni = 0; ni < 4; ni++) {
            const int c = ecol + ni * 8;
            float v00 = acc[mi * 4 + ni][0] + sBias[c + 0];
            float v01 = acc[mi * 4 + ni][1] + sBias[c + 1];
            float v10 = acc[mi * 4 + ni][2] + sBias[c + 0];
            float v11 = acc[mi * 4 + ni][3] + sBias[c + 1];
            if (which == 0) {
                // Q: write fp16 hi into g_qs[h][row][64]
                const int gcol = n0 + c;
                const int hh = gcol >> 6, d = gcol & 63;
                __half* p0 = g_qs + ((size_t)hh * ROWS + r0) * 64 + d;
                __half* p1 = g_qs + ((size_t)hh * ROWS + r1) * 64 + d;
                *(__half2*)p0 = __half2(__float2half(v00), __float2half(v01));
                *(__half2*)p1 = __half2(__float2half(v10), __float2half(v11));
            } else {
                float* p0 = Y + (size_t)r0 * DMODEL + n0 + c;
                float* p1 = Y + (size_t)r1 * DMODEL + n0 + c;
                *(float2*)p0 = make_float2(v00 * mv0, v01 * mv0);
                *(float2*)p1 = make_float2(v10 * mv1, v11 * mv1);
            }
        }
    }
}

// ---------------------------------------------------------------------------
// M[b,h] += K'[b,h]^T @ V[b,h] over a 64-key slice (split-K 32 + atomics)
// grid = (32, 32), 256 threads
// ---------------------------------------------------------------------------
__global__ __launch_bounds__(256)
void kv_outer()
{
    const int bh = blockIdx.x;
    const int b = bh >> 4, h = bh & 15;
    const int kstart = blockIdx.y * 64;

    __shared__ float Ks[32][64];
    __shared__ float Vs[32][64];

    const int tid = threadIdx.x;
    const int tx = tid & 15, ty = tid >> 4;

    float acc[4][4];
#pragma unroll
    for (int i = 0; i < 4; i++)
#pragma unroll
        for (int j = 0; j < 4; j++) acc[i][j] = 0.0f;

    const int lr = tid >> 3;
    const int lc = (tid & 7) * 8;

    for (int kc = 0; kc < 2; kc++) {
        const size_t base = (size_t)(b * SEQ + kstart + kc * 32 + lr) * DMODEL + h * HDIM + lc;
        *(float4*)(&Ks[lr][lc])     = *(const float4*)(g_k + base);
        *(float4*)(&Ks[lr][lc + 4]) = *(const float4*)(g_k + base + 4);
        *(float4*)(&Vs[lr][lc])     = *(const float4*)(g_v + base);
        *(float4*)(&Vs[lr][lc + 4]) = *(const float4*)(g_v + base + 4);
        __syncthreads();

#pragma unroll
        for (int kk = 0; kk < 32; kk++) {
            const float4 a4 = *(const float4*)(&Ks[kk][ty * 4]);
            const float4 b4 = *(const float4*)(&Vs[kk][tx * 4]);
            const float a[4] = {a4.x, a4.y, a4.z, a4.w};
            const float bb[4] = {b4.x, b4.y, b4.z, b4.w};
#pragma unroll
            for (int i = 0; i < 4; i++)
#pragma unroll
                for (int j = 0; j < 4; j++)
                    acc[i][j] += a[i] * bb[j];
        }
        __syncthreads();
    }

    float* Mout = g_m + (size_t)bh * HDIM * HDIM;
#pragma unroll
    for (int i = 0; i < 4; i++)
#pragma unroll
        for (int j = 0; j < 4; j++)
            atomicAdd(&Mout[(ty * 4 + i) * HDIM + tx * 4 + j], acc[i][j]);
}

// ---------------------------------------------------------------------------
// ctx = Q_hi @ M_hi via mma.sync fp16, K=64 (4 k16 steps).
// grid (16 stile, 16 h, 2 b), 256 threads, 8 warps (2M x 4N).
// dynamic smem: A 16KB @0, B 8KB @16384, Mfp32 16KB @24576 = 40KB
// ---------------------------------------------------------------------------
#define CTX_SMEM (16384 + 8192 + 16384)

__global__ __launch_bounds__(256)
void ctx_mma(float* __restrict__ out)
{
    extern __shared__ __align__(1024) uint8_t smem[];
    const uint32_t sbase = smem_to_u32(smem);
    const uint32_t sB = sbase + 16384;
    float* sM = (float*)(smem + 24576);

    const int tid  = threadIdx.x;
    const int wid  = tid >> 5;
    const int lane = tid & 31;
    const int st = blockIdx.x, h = blockIdx.y, b = blockIdx.z;
    const int s0 = st * 128;
    const size_t arow0 = (size_t)h * ROWS + b * SEQ + s0;

    // 1. stage A (Q_hi, 128 rows x 64 halfs = 128B/row) via cp.async
    {
        const int srow = tid >> 3;    // 0..31
        const int sc   = tid & 7;
#pragma unroll
        for (int p = 0; p < 4; p++) {
            const int row = srow + p * 32;
            CP_ASYNC16(sbase + SWZ128((uint32_t)(row * 128 + sc * 16)),
                       g_qs + (arow0 + row) * 64 + sc * 8);
        }
        CP_COMMIT();
    }

    // 2. load M (fp32 64x64) coalesced
    {
        const float* Msrc = g_m + (size_t)(b * NHEAD + h) * HDIM * HDIM;
#pragma unroll
        for (int i = 0; i < 4; i++) {
            int idx = tid * 16 + i * 4;
            *(float4*)(sM + idx) = *(const float4*)(Msrc + idx);
        }
    }
    __syncthreads();

    // 3. transpose-convert to fp16 B[j][k] = hi(M[k][j]), swizzled (128B rows)
    {
        const int j  = tid >> 2;
        const int k0 = (tid & 3) * 16;
#pragma unroll
        for (int i = 0; i < 16; i++) {
            const int k = k0 + i;
            const uint32_t bo = (uint32_t)(j * 128 + k * 2);
            *(__half*)(smem + 16384 + SWZ128(bo)) = __float2half(sM[k * 64 + j]);
        }
    }
    CP_WAIT0();
    __syncthreads();

    // 4. MMA: warp tile 64 M x 16 N, K = 64 (4 k16 steps)
    const int wm0 = (wid & 1) * 64;
    const int wn0 = (wid >> 1) * 16;

    float acc[8][4];
#pragma unroll
    for (int i = 0; i < 8; i++)
#pragma unroll
        for (int j = 0; j < 4; j++) acc[i][j] = 0.0f;

    const int a_row = wm0 + (lane & 15);
    const int a_ch  = (lane >> 4);
    const int b_g   = lane >> 3;
    const int b_row = wn0 + ((b_g >> 1) << 3) + (lane & 7);
    const int b_ch  = (b_g & 1);

#pragma unroll
    for (int ks = 0; ks < 4; ks++) {
        const int ch_a = ks * 2 + a_ch;
        const int ch_b = ks * 2 + b_ch;
        uint32_t a[4][4];
#pragma unroll
        for (int mi = 0; mi < 4; mi++)
            ldsm_x4(a[mi][0], a[mi][1], a[mi][2], a[mi][3],
                    sbase + SWZ128((uint32_t)((a_row + mi * 16) * 128 + ch_a * 16)));
        uint32_t bb[4];
        ldsm_x4(bb[0], bb[1], bb[2], bb[3],
                sB + SWZ128((uint32_t)(b_row * 128 + ch_b * 16)));
#pragma unroll
        for (int mi = 0; mi < 4; mi++)
#pragma unroll
            for (int ni = 0; ni < 2; ni++)
                mma_f16(acc[mi * 2 + ni], a[mi][0], a[mi][1], a[mi][2], a[mi][3],
                        bb[ni * 2], bb[ni * 2 + 1]);
    }

    // 5. epilogue
    const int erow = wm0 + (lane >> 2);
    const int ecol = wn0 + (lane & 3) * 2;
#pragma unroll
    for (int mi = 0; mi < 4; mi++) {
        const int r0 = s0 + erow + mi * 16;
        const int r1 = r0 + 8;
#pragma unroll
        for (int ni = 0; ni < 2; ni++) {
            const int c = h * HDIM + ecol + ni * 8;
            float* p0 = out + (size_t)(b * SEQ + r0) * DMODEL + c;
            float* p1 = out + (size_t)(b * SEQ + r1) * DMODEL + c;
            *(float2*)p0 = make_float2(acc[mi * 2 + ni][0], acc[mi * 2 + ni][1]);
            *(float2*)p1 = make_float2(acc[mi * 2 + ni][2], acc[mi * 2 + ni][3]);
        }
    }
}

// ---------------------------------------------------------------------------
// Launch: two-branch graph; join at ctx_mma.
// ---------------------------------------------------------------------------
extern "C" void kernel_launch(void* const* d_in, const int* in_sizes, int n_in,
                              void* d_out, int out_size)
{
    const float* X     = (const float*)d_in[0];
    const float* amask = (const float*)d_in[1];
    const float* Wq    = (const float*)d_in[2];
    const float* bq    = (const float*)d_in[3];
    const float* Wk    = (const float*)d_in[4];
    const float* bk    = (const float*)d_in[5];
    const float* Wv    = (const float*)d_in[6];
    const float* bv    = (const float*)d_in[7];
    float* out = (float*)d_out;

    static cudaStream_t s_kv = nullptr, s_q = nullptr;
    static cudaEvent_t ev_fork = nullptr, ev_convx = nullptr, ev_convw = nullptr,
                       ev_kv = nullptr, ev_q = nullptr;
    if (s_kv == nullptr) {
        cudaStreamCreateWithFlags(&s_kv, cudaStreamNonBlocking);
        cudaStreamCreateWithFlags(&s_q,  cudaStreamNonBlocking);
        cudaEventCreateWithFlags(&ev_fork,  cudaEventDisableTiming);
        cudaEventCreateWithFlags(&ev_convx, cudaEventDisableTiming);
        cudaEventCreateWithFlags(&ev_convw, cudaEventDisableTiming);
        cudaEventCreateWithFlags(&ev_kv,    cudaEventDisableTiming);
        cudaEventCreateWithFlags(&ev_q,     cudaEventDisableTiming);
        cudaFuncSetAttribute(qkv_mma, cudaFuncAttributeMaxDynamicSharedMemorySize,
                             2 * BUF_BYTES);
        cudaFuncSetAttribute(ctx_mma, cudaFuncAttributeMaxDynamicSharedMemorySize,
                             CTX_SMEM);
    }

    // fork both worker streams off the capture (default) stream
    cudaEventRecord(ev_fork, 0);
    cudaStreamWaitEvent(s_kv, ev_fork, 0);
    cudaStreamWaitEvent(s_q,  ev_fork, 0);

    // branch heads (independent)
    conv_x<<<ELEMS / 4 / 256, 256, 0, s_kv>>>(X);                       // X_hi + zero_m
    cudaEventRecord(ev_convx, s_kv);
    conv_w<<<dim3(DMODEL * DMODEL / 4 / 256, 3), 256, 0, s_q>>>(Wq, Wk, Wv);
    cudaEventRecord(ev_convw, s_q);

    // KV branch
    cudaStreamWaitEvent(s_kv, ev_convw, 0);
    qkv_mma<<<dim3(8, 32, 2), 256, 2 * BUF_BYTES, s_kv>>>(1, amask, bq, bk, bv); // K,V
    kv_outer<<<dim3(BATCH * NHEAD, 32), 256, 0, s_kv>>>();
    cudaEventRecord(ev_kv, s_kv);

    // Q branch
    cudaStreamWaitEvent(s_q, ev_convx, 0);
    qkv_mma<<<dim3(8, 32, 1), 256, 2 * BUF_BYTES, s_q>>>(0, amask, bq, bk, bv);  // Q
    cudaEventRecord(ev_q, s_q);

    // join on capture stream, final kernel
    cudaStreamWaitEvent(0, ev_kv, 0);
    cudaStreamWaitEvent(0, ev_q, 0);
    ctx_mma<<<dim3(SEQ / 128, NHEAD, BATCH), 256, CTX_SMEM>>>(out);
}

// round 15
// speedup vs baseline: 2.5826x; 1.1293x over previous
#include <cuda_runtime.h>
#include <cuda_fp16.h>
#include <cstdint>

// Problem constants
#define BATCH 2
#define SEQ   2048
#define DMODEL 1024
#define NHEAD 16
#define HDIM  64
#define ROWS  (BATCH*SEQ)          // 4096
#define ELEMS (ROWS*DMODEL)        // 4,194,304
#define KEFF  1024                 // hi-only fp16, K = DMODEL

// Scratch (static __device__ globals — allocation-free per harness rules)
__device__ float g_m[BATCH*NHEAD*HDIM*HDIM];   // 131072 floats
__device__ __half g_qs[(size_t)NHEAD*ROWS*64];     // Q_hi [h][row][64] 8MB
__device__ __half g_kh[(size_t)NHEAD*ROWS*64];     // K'_hi (masked)    8MB
__device__ __half g_vh[(size_t)NHEAD*ROWS*64];     // V_hi              8MB
__device__ __half g_abar[(size_t)ROWS*KEFF];       // X_hi [4096,1024]  8MB
__device__ __half g_bbar[(size_t)3*DMODEL*KEFF];   // W_hi 3x[1024,1024] 6MB

// ---------------------------------------------------------------------------
// Base-target (sm_80+) PTX helpers: ldmatrix / mma.sync / cp.async
// ---------------------------------------------------------------------------
__device__ __forceinline__ uint32_t smem_to_u32(const void* p) {
    uint32_t a;
    asm("{ .reg .u64 t; cvta.to.shared.u64 t, %1; cvt.u32.u64 %0, t; }" : "=r"(a) : "l"(p));
    return a;
}
__device__ __forceinline__ void ldsm_x4(uint32_t& r0, uint32_t& r1, uint32_t& r2, uint32_t& r3,
                                        uint32_t addr) {
    asm volatile("ldmatrix.sync.aligned.m8n8.x4.shared.b16 {%0,%1,%2,%3}, [%4];"
                 : "=r"(r0), "=r"(r1), "=r"(r2), "=r"(r3) : "r"(addr));
}
__device__ __forceinline__ void ldsm_x4_t(uint32_t& r0, uint32_t& r1, uint32_t& r2, uint32_t& r3,
                                          uint32_t addr) {
    asm volatile("ldmatrix.sync.aligned.m8n8.x4.trans.shared.b16 {%0,%1,%2,%3}, [%4];"
                 : "=r"(r0), "=r"(r1), "=r"(r2), "=r"(r3) : "r"(addr));
}
__device__ __forceinline__ void mma_f16(float* d, uint32_t a0, uint32_t a1, uint32_t a2,
                                        uint32_t a3, uint32_t b0, uint32_t b1) {
    asm volatile("mma.sync.aligned.m16n8k16.row.col.f32.f16.f16.f32 "
                 "{%0,%1,%2,%3}, {%4,%5,%6,%7}, {%8,%9}, {%0,%1,%2,%3};"
                 : "+f"(d[0]), "+f"(d[1]), "+f"(d[2]), "+f"(d[3])
                 : "r"(a0), "r"(a1), "r"(a2), "r"(a3), "r"(b0), "r"(b1));
}
#define CP_ASYNC16(saddr, gptr) \
    asm volatile("cp.async.cg.shared.global [%0], [%1], 16;" :: "r"(saddr), "l"(gptr))
#define CP_COMMIT() asm volatile("cp.async.commit_group;" ::: "memory")
#define CP_WAIT1()  asm volatile("cp.async.wait_group 1;" ::: "memory")
#define CP_WAIT0()  asm volatile("cp.async.wait_group 0;" ::: "memory")

// SW128 swizzle: rows of 128B, chunk16B index ^= (row & 7)
#define SWZ128(bo) ((bo) ^ (((bo) >> 3) & 0x70))

// ---------------------------------------------------------------------------
// X -> X_hi (fp16). Also zeroes g_m.
// ---------------------------------------------------------------------------
__global__ __launch_bounds__(256) void conv_x(const float* __restrict__ X)
{
    if (blockIdx.x < 512) g_m[blockIdx.x * 256 + threadIdx.x] = 0.0f;

    int t = blockIdx.x * 256 + threadIdx.x;
    int idx = t * 4;
    float4 v = *(const float4*)(X + idx);
    __half* base = g_abar + idx;
    *(__half2*)(base)     = __half2(__float2half(v.x), __float2half(v.y));
    *(__half2*)(base + 2) = __half2(__float2half(v.z), __float2half(v.w));
}

// W -> W_hi (fp16), 3 slabs
__global__ __launch_bounds__(256) void conv_w(const float* __restrict__ Wq,
                                              const float* __restrict__ Wk,
                                              const float* __restrict__ Wv)
{
    int which = blockIdx.y;
    const float* __restrict__ W = (which == 0) ? Wq : (which == 1) ? Wk : Wv;
    int t = blockIdx.x * 256 + threadIdx.x;
    int idx = t * 4;
    float4 v = *(const float4*)(W + idx);
    __half* base = g_bbar + (size_t)which * DMODEL * KEFF + idx;
    *(__half2*)(base)     = __half2(__float2half(v.x), __float2half(v.y));
    *(__half2*)(base + 2) = __half2(__float2half(v.z), __float2half(v.w));
}

// ---------------------------------------------------------------------------
// mma.sync fp16 projection (hi*hi, K=1024, NIT=16).
// slab 0 -> g_qs (+bq); slab 1 -> g_kh (mask,+bk); slab 2 -> g_vh (+bv)
// All outputs fp16 in [h][row][64] layout.
// CTA 128x128, BK=64, 8 warps (2x4), warp tile 64x32, 2-stage cp.async,
// 2 CTAs/SM. dynamic smem = 64KB
// ---------------------------------------------------------------------------
#define BKC 64
#define NITER (KEFF / BKC)   // 16
#define CHUNK_BYTES 16384    // 128 rows * 128B
#define BUF_BYTES   32768    // A chunk + B chunk

__global__ __launch_bounds__(256, 2)
void qkv_mma(int zbase,
             const float* __restrict__ amask,
             const float* __restrict__ bq,
             const float* __restrict__ bk,
             const float* __restrict__ bv)
{
    extern __shared__ __align__(1024) uint8_t smem[];
    __shared__ float sBias[128];

    const int tid  = threadIdx.x;
    const int wid  = tid >> 5;
    const int lane = tid & 31;
    const int which = blockIdx.z + zbase;
    const int m0 = blockIdx.y * 128;
    const int n0 = blockIdx.x * 128;

    const float* __restrict__ bias = (which == 0) ? bq : (which == 1) ? bk : bv;
    __half* __restrict__ Yh = (which == 0) ? g_qs : (which == 1) ? g_kh : g_vh;

    const __half* __restrict__ Ag = g_abar;
    const __half* __restrict__ Bg = g_bbar + (size_t)which * DMODEL * KEFF;

    const uint32_t sbase = smem_to_u32(smem);

    if (tid < 128) sBias[tid] = bias[n0 + tid];

    const int srow = tid >> 3;        // 0..31
    const int sc   = tid & 7;         // 16B chunk within 128B row

    auto stage = [&](int buf, int it) {
        const int ke = it * BKC;
        const uint32_t abase = sbase + buf * BUF_BYTES;
        const uint32_t bbase = abase + CHUNK_BYTES;
#pragma unroll
        for (int p = 0; p < 4; p++) {
            const int row = srow + p * 32;
            const uint32_t so = SWZ128((uint32_t)(row * 128 + sc * 16));
            CP_ASYNC16(abase + so, Ag + (size_t)(m0 + row) * KEFF + ke + sc * 8);
            CP_ASYNC16(bbase + so, Bg + (size_t)(n0 + row) * KEFF + ke + sc * 8);
        }
    };

    // warp tiling: 2 warps along M, 4 along N
    const int wm0 = (wid & 1) * 64;
    const int wn0 = (wid >> 1) * 32;

    float acc[16][4];
#pragma unroll
    for (int i = 0; i < 16; i++)
#pragma unroll
        for (int j = 0; j < 4; j++) acc[i][j] = 0.0f;

    const int a_row = wm0 + (lane & 15);
    const int a_ch  = (lane >> 4);
    const int b_g   = lane >> 3;
    const int b_row = wn0 + ((b_g >> 1) << 3) + (lane & 7);
    const int b_ch  = (b_g & 1);

    stage(0, 0);
    CP_COMMIT();

    for (int it = 0; it < NITER; it++) {
        if (it + 1 < NITER) {
            stage((it + 1) & 1, it + 1);
            CP_COMMIT();
            CP_WAIT1();
        } else {
            CP_WAIT0();
        }
        __syncthreads();

        const uint32_t abase = sbase + (it & 1) * BUF_BYTES;
        const uint32_t bbase = abase + CHUNK_BYTES;

#pragma unroll
        for (int ks = 0; ks < 4; ks++) {
            uint32_t a[4][4];
#pragma unroll
            for (int mi = 0; mi < 4; mi++) {
                const int row = a_row + mi * 16;
                const int ch  = ks * 2 + a_ch;
                ldsm_x4(a[mi][0], a[mi][1], a[mi][2], a[mi][3],
                        abase + SWZ128((uint32_t)(row * 128 + ch * 16)));
            }
            uint32_t b[2][4];
#pragma unroll
            for (int np = 0; np < 2; np++) {
                const int row = b_row + np * 16;
                const int ch  = ks * 2 + b_ch;
                ldsm_x4(b[np][0], b[np][1], b[np][2], b[np][3],
                        bbase + SWZ128((uint32_t)(row * 128 + ch * 16)));
            }
#pragma unroll
            for (int mi = 0; mi < 4; mi++)
#pragma unroll
                for (int ni = 0; ni < 4; ni++) {
                    const int np = ni >> 1, hf = (ni & 1) * 2;
                    mma_f16(acc[mi * 4 + ni], a[mi][0], a[mi][1], a[mi][2], a[mi][3],
                            b[np][hf], b[np][hf + 1]);
                }
        }
        __syncthreads();
    }

    // Epilogue: fp16 to [h][row][64] (mask for K)
    const int erow = wm0 + (lane >> 2);
    const int ecol = wn0 + (lane & 3) * 2;
#pragma unroll
    for (int mi = 0; mi < 4; mi++) {
        const int r0 = m0 + erow + mi * 16;
        const int r1 = r0 + 8;
        float mv0 = 1.0f, mv1 = 1.0f;
        if (which == 1) {
            mv0 = (amask[r0] >= 0.0f) ? 1.0f : 0.0f;
            mv1 = (amask[r1] >= 0.0f) ? 1.0f : 0.0f;
        }
#pragma unroll
        for (int ni = 0; ni < 4; ni++) {
            const int c = ecol + ni * 8;
            float v00 = (acc[mi * 4 + ni][0] + sBias[c + 0]) * mv0;
            float v01 = (acc[mi * 4 + ni][1] + sBias[c + 1]) * mv0;
            float v10 = (acc[mi * 4 + ni][2] + sBias[c + 0]) * mv1;
            float v11 = (acc[mi * 4 + ni][3] + sBias[c + 1]) * mv1;
            const int gcol = n0 + c;
            const int hh = gcol >> 6, d = gcol & 63;
            __half* p0 = Yh + ((size_t)hh * ROWS + r0) * 64 + d;
            __half* p1 = Yh + ((size_t)hh * ROWS + r1) * 64 + d;
            *(__half2*)p0 = __half2(__float2half(v00), __float2half(v01));
            *(__half2*)p1 = __half2(__float2half(v10), __float2half(v11));
        }
    }
}

// ---------------------------------------------------------------------------
// M[b,h] += K'[b,h]^T @ V[b,h] over a 128-key slice, tensor cores.
// A = K'^T (ldmatrix.trans), B = V (col-major via ldmatrix.trans).
// grid (32 bh, 16 splits), 128 threads (4 warps: M=64, N=16 each).
// ---------------------------------------------------------------------------
__global__ __launch_bounds__(128)
void kv_mma()
{
    __shared__ __align__(1024) uint8_t sK[16384];   // 128 keys x 64 halfs (128B rows)
    __shared__ __align__(1024) uint8_t sV[16384];

    const int tid  = threadIdx.x;
    const int wid  = tid >> 5;
    const int lane = tid & 31;
    const int bh = blockIdx.x;
    const int b = bh >> 4, h = bh & 15;
    const int kbase = blockIdx.y * 128;

    const uint32_t sKb = smem_to_u32(sK);
    const uint32_t sVb = smem_to_u32(sV);

    // load 128 keys x 128B per tile; thread t owns row t (8 chunks)
    {
        const size_t grow = ((size_t)h * ROWS + b * SEQ + kbase + tid) * 64;
#pragma unroll
        for (int c = 0; c < 8; c++) {
            const uint32_t so = SWZ128((uint32_t)(tid * 128 + c * 16));
            CP_ASYNC16(sKb + so, g_kh + grow + c * 8);
            CP_ASYNC16(sVb + so, g_vh + grow + c * 8);
        }
        CP_COMMIT();
    }
    CP_WAIT0();
    __syncthreads();

    const int wn0 = wid * 16;

    float acc[4][2][4];
#pragma unroll
    for (int i = 0; i < 4; i++)
#pragma unroll
        for (int j = 0; j < 2; j++)
#pragma unroll
            for (int k = 0; k < 4; k++) acc[i][j][k] = 0.0f;

    // lane components for trans loads
    const int ka_key = (lane & 7) + ((lane >> 4) & 1) * 8;   // + kk*16
    const int ka_dim = ((lane >> 3) & 1) * 8;                // + mi*16
    const int kb_key = (lane & 7) + ((lane >> 3) & 1) * 8;   // + kk*16
    const int kb_dim = wn0 + ((lane >> 4) & 1) * 8;

#pragma unroll
    for (int kk = 0; kk < 8; kk++) {
        uint32_t a[4][4];
#pragma unroll
        for (int mi = 0; mi < 4; mi++) {
            const int key = kk * 16 + ka_key;
            const int dim = mi * 16 + ka_dim;
            ldsm_x4_t(a[mi][0], a[mi][1], a[mi][2], a[mi][3],
                      sKb + SWZ128((uint32_t)(key * 128 + dim * 2)));
        }
        uint32_t bb[4];
        {
            const int key = kk * 16 + kb_key;
            ldsm_x4_t(bb[0], bb[1], bb[2], bb[3],
                      sVb + SWZ128((uint32_t)(key * 128 + kb_dim * 2)));
        }
#pragma unroll
        for (int mi = 0; mi < 4; mi++)
#pragma unroll
            for (int ni = 0; ni < 2; ni++)
                mma_f16(acc[mi][ni], a[mi][0], a[mi][1], a[mi][2], a[mi][3],
                        bb[ni * 2], bb[ni * 2 + 1]);
    }

    float* Mout = g_m + (size_t)bh * HDIM * HDIM;
    const int em = lane >> 2;
    const int en = (lane & 3) * 2;
#pragma unroll
    for (int mi = 0; mi < 4; mi++) {
        const int m = mi * 16 + em;
#pragma unroll
        for (int ni = 0; ni < 2; ni++) {
            const int n = wn0 + ni * 8 + en;
            atomicAdd(&Mout[m * HDIM + n],           acc[mi][ni][0]);
            atomicAdd(&Mout[m * HDIM + n + 1],       acc[mi][ni][1]);
            atomicAdd(&Mout[(m + 8) * HDIM + n],     acc[mi][ni][2]);
            atomicAdd(&Mout[(m + 8) * HDIM + n + 1], acc[mi][ni][3]);
        }
    }
}

// ---------------------------------------------------------------------------
// ctx = Q_hi @ M_hi via mma.sync fp16, K=64 (4 k16 steps).
// grid (16 stile, 16 h, 2 b), 256 threads, 8 warps (2M x 4N).
// dynamic smem: A 16KB @0, B 8KB @16384, Mfp32 16KB @24576 = 40KB
// ---------------------------------------------------------------------------
#define CTX_SMEM (16384 + 8192 + 16384)

__global__ __launch_bounds__(256)
void ctx_mma(float* __restrict__ out)
{
    extern __shared__ __align__(1024) uint8_t smem[];
    const uint32_t sbase = smem_to_u32(smem);
    const uint32_t sB = sbase + 16384;
    float* sM = (float*)(smem + 24576);

    const int tid  = threadIdx.x;
    const int wid  = tid >> 5;
    const int lane = tid & 31;
    const int st = blockIdx.x, h = blockIdx.y, b = blockIdx.z;
    const int s0 = st * 128;
    const size_t arow0 = (size_t)h * ROWS + b * SEQ + s0;

    // 1. stage A (Q_hi, 128 rows x 64 halfs = 128B/row) via cp.async
    {
        const int srow = tid >> 3;    // 0..31
        const int sc   = tid & 7;
#pragma unroll
        for (int p = 0; p < 4; p++) {
            const int row = srow + p * 32;
            CP_ASYNC16(sbase + SWZ128((uint32_t)(row * 128 + sc * 16)),
                       g_qs + (arow0 + row) * 64 + sc * 8);
        }
        CP_COMMIT();
    }

    // 2. load M (fp32 64x64) coalesced
    {
        const float* Msrc = g_m + (size_t)(b * NHEAD + h) * HDIM * HDIM;
#pragma unroll
        for (int i = 0; i < 4; i++) {
            int idx = tid * 16 + i * 4;
            *(float4*)(sM + idx) = *(const float4*)(Msrc + idx);
        }
    }
    __syncthreads();

    // 3. transpose-convert to fp16 B[j][k] = hi(M[k][j]), swizzled (128B rows)
    {
        const int j  = tid >> 2;
        const int k0 = (tid & 3) * 16;
#pragma unroll
        for (int i = 0; i < 16; i++) {
            const int k = k0 + i;
            const uint32_t bo = (uint32_t)(j * 128 + k * 2);
            *(__half*)(smem + 16384 + SWZ128(bo)) = __float2half(sM[k * 64 + j]);
        }
    }
    CP_WAIT0();
    __syncthreads();

    // 4. MMA: warp tile 64 M x 16 N, K = 64 (4 k16 steps)
    const int wm0 = (wid & 1) * 64;
    const int wn0 = (wid >> 1) * 16;

    float acc[8][4];
#pragma unroll
    for (int i = 0; i < 8; i++)
#pragma unroll
        for (int j = 0; j < 4; j++) acc[i][j] = 0.0f;

    const int a_row = wm0 + (lane & 15);
    const int a_ch  = (lane >> 4);
    const int b_g   = lane >> 3;
    const int b_row = wn0 + ((b_g >> 1) << 3) + (lane & 7);
    const int b_ch  = (b_g & 1);

#pragma unroll
    for (int ks = 0; ks < 4; ks++) {
        const int ch_a = ks * 2 + a_ch;
        const int ch_b = ks * 2 + b_ch;
        uint32_t a[4][4];
#pragma unroll
        for (int mi = 0; mi < 4; mi++)
            ldsm_x4(a[mi][0], a[mi][1], a[mi][2], a[mi][3],
                    sbase + SWZ128((uint32_t)((a_row + mi * 16) * 128 + ch_a * 16)));
        uint32_t bb[4];
        ldsm_x4(bb[0], bb[1], bb[2], bb[3],
                sB + SWZ128((uint32_t)(b_row * 128 + ch_b * 16)));
#pragma unroll
        for (int mi = 0; mi < 4; mi++)
#pragma unroll
            for (int ni = 0; ni < 2; ni++)
                mma_f16(acc[mi * 2 + ni], a[mi][0], a[mi][1], a[mi][2], a[mi][3],
                        bb[ni * 2], bb[ni * 2 + 1]);
    }

    // 5. epilogue
    const int erow = wm0 + (lane >> 2);
    const int ecol = wn0 + (lane & 3) * 2;
#pragma unroll
    for (int mi = 0; mi < 4; mi++) {
        const int r0 = s0 + erow + mi * 16;
        const int r1 = r0 + 8;
#pragma unroll
        for (int ni = 0; ni < 2; ni++) {
            const int c = h * HDIM + ecol + ni * 8;
            float* p0 = out + (size_t)(b * SEQ + r0) * DMODEL + c;
            float* p1 = out + (size_t)(b * SEQ + r1) * DMODEL + c;
            *(float2*)p0 = make_float2(acc[mi * 2 + ni][0], acc[mi * 2 + ni][1]);
            *(float2*)p1 = make_float2(acc[mi * 2 + ni][2], acc[mi * 2 + ni][3]);
        }
    }
}

// ---------------------------------------------------------------------------
// Launch: two-branch graph; join at ctx_mma.
// ---------------------------------------------------------------------------
extern "C" void kernel_launch(void* const* d_in, const int* in_sizes, int n_in,
                              void* d_out, int out_size)
{
    const float* X     = (const float*)d_in[0];
    const float* amask = (const float*)d_in[1];
    const float* Wq    = (const float*)d_in[2];
    const float* bq    = (const float*)d_in[3];
    const float* Wk    = (const float*)d_in[4];
    const float* bk    = (const float*)d_in[5];
    const float* Wv    = (const float*)d_in[6];
    const float* bv    = (const float*)d_in[7];
    float* out = (float*)d_out;

    static cudaStream_t s_kv = nullptr, s_q = nullptr;
    static cudaEvent_t ev_fork = nullptr, ev_convx = nullptr, ev_convw = nullptr,
                       ev_kv = nullptr, ev_q = nullptr;
    if (s_kv == nullptr) {
        cudaStreamCreateWithFlags(&s_kv, cudaStreamNonBlocking);
        cudaStreamCreateWithFlags(&s_q,  cudaStreamNonBlocking);
        cudaEventCreateWithFlags(&ev_fork,  cudaEventDisableTiming);
        cudaEventCreateWithFlags(&ev_convx, cudaEventDisableTiming);
        cudaEventCreateWithFlags(&ev_convw, cudaEventDisableTiming);
        cudaEventCreateWithFlags(&ev_kv,    cudaEventDisableTiming);
        cudaEventCreateWithFlags(&ev_q,     cudaEventDisableTiming);
        cudaFuncSetAttribute(qkv_mma, cudaFuncAttributeMaxDynamicSharedMemorySize,
                             2 * BUF_BYTES);
        cudaFuncSetAttribute(ctx_mma, cudaFuncAttributeMaxDynamicSharedMemorySize,
                             CTX_SMEM);
    }

    // fork both worker streams off the capture (default) stream
    cudaEventRecord(ev_fork, 0);
    cudaStreamWaitEvent(s_kv, ev_fork, 0);
    cudaStreamWaitEvent(s_q,  ev_fork, 0);

    // branch heads (independent)
    conv_x<<<ELEMS / 4 / 256, 256, 0, s_kv>>>(X);                       // X_hi + zero_m
    cudaEventRecord(ev_convx, s_kv);
    conv_w<<<dim3(DMODEL * DMODEL / 4 / 256, 3), 256, 0, s_q>>>(Wq, Wk, Wv);
    cudaEventRecord(ev_convw, s_q);

    // KV branch
    cudaStreamWaitEvent(s_kv, ev_convw, 0);
    qkv_mma<<<dim3(8, 32, 2), 256, 2 * BUF_BYTES, s_kv>>>(1, amask, bq, bk, bv); // K,V
    kv_mma<<<dim3(BATCH * NHEAD, 16), 128, 0, s_kv>>>();
    cudaEventRecord(ev_kv, s_kv);

    // Q branch
    cudaStreamWaitEvent(s_q, ev_convx, 0);
    qkv_mma<<<dim3(8, 32, 1), 256, 2 * BUF_BYTES, s_q>>>(0, amask, bq, bk, bv);  // Q
    cudaEventRecord(ev_q, s_q);

    // join on capture stream, final kernel
    cudaStreamWaitEvent(0, ev_kv, 0);
    cudaStreamWaitEvent(0, ev_q, 0);
    ctx_mma<<<dim3(SEQ / 128, NHEAD, BATCH), 256, CTX_SMEM>>>(out);
}